// round 10
// baseline (speedup 1.0000x reference)
#include <cuda_runtime.h>
#include <cuda.h>
#include <cuda_fp16.h>
#include <cstdint>

#define NE 16
#define NT 512
#define NH 2048
#define NI 4096

// scratch (allocation-free rule: __device__ globals)
__device__ __align__(1024) __half g_act_h[(size_t)NE * NT * NI];      // 67MB
__device__ __align__(1024) __half g_xh[(size_t)NE * NT * NH];         // 34MB
__device__ __align__(1024) __half g_w1h[(size_t)NE * 2 * NI * NH];    // 537MB
__device__ __align__(1024) __half g_w2h[(size_t)NE * NH * NI];        // 268MB
__device__ int g_flag[NE];

// ---------------- device helpers ----------------
__device__ __forceinline__ uint32_t smem_u32(const void* p) {
    uint32_t a;
    asm("{ .reg .u64 t; cvta.to.shared.u64 t, %1; cvt.u32.u64 %0, t; }" : "=r"(a) : "l"(p));
    return a;
}

#define MBAR_INIT(addr, cnt) \
    asm volatile("mbarrier.init.shared.b64 [%0], %1;" :: "r"(addr), "r"(cnt) : "memory")
#define MBAR_EXPECT_TX(addr, bytes) \
    asm volatile("mbarrier.arrive.expect_tx.shared.b64 _, [%0], %1;" :: "r"(addr), "r"(bytes) : "memory")
#define MBAR_ARRIVE(addr) \
    asm volatile("mbarrier.arrive.shared.b64 _, [%0];" :: "r"(addr) : "memory")
#define WAIT_PAR(addr, ph) do {                                                  \
    uint32_t _a = (addr), _p = (ph);                                             \
    asm volatile("{\n\t.reg .pred P;\n\t"                                        \
                 "WL_%=:\n\t"                                                    \
                 "mbarrier.try_wait.parity.shared.b64 P, [%0], %1, 0x989680;\n\t"\
                 "@!P bra WL_%=;\n\t}" :: "r"(_a), "r"(_p) : "memory");          \
} while (0)

#define OPAQUE(x) asm volatile("" : "+r"(x))

#define TMA2D(smem, map, x, y, mbar)                                                          \
    asm volatile("cp.async.bulk.tensor.2d.shared::cta.global.tile.mbarrier::complete_tx::bytes " \
                 "[%0], [%1, {%2, %3}], [%4];"                                                \
                 :: "r"(smem), "l"(map), "r"(x), "r"(y), "r"(mbar) : "memory")

__device__ __forceinline__ uint32_t lds_u32(uint32_t addr) {
    uint32_t v;
    asm("ld.shared.b32 %0, [%1];" : "=r"(v) : "r"(addr));
    return v;
}

__device__ __forceinline__ uint32_t pack_h2(float lo, float hi) {
    uint32_t r;
    asm("{\n\t.reg .b16 a, b;\n\tcvt.rn.f16.f32 a, %1;\n\tcvt.rn.f16.f32 b, %2;\n\t"
        "mov.b32 %0, {a, b};\n\t}" : "=r"(r) : "f"(lo), "f"(hi));
    return r;
}

__device__ __forceinline__ int acq_ld(const int* p) {
    int v;
    asm volatile("ld.acquire.gpu.global.b32 %0, [%1];" : "=r"(v) : "l"(p));
    return v;
}

#define MMA_F16(c, a0, a1, a2, a3, b0, b1)                                       \
    asm volatile("mma.sync.aligned.m16n8k16.row.col.f32.f16.f16.f32 "            \
                 "{%0,%1,%2,%3}, {%4,%5,%6,%7}, {%8,%9}, {%0,%1,%2,%3};"         \
                 : "+f"((c)[0]), "+f"((c)[1]), "+f"((c)[2]), "+f"((c)[3])        \
                 : "r"(a0), "r"(a1), "r"(a2), "r"(a3), "r"(b0), "r"(b1))

static constexpr uint32_t STAGES = 3;
static constexpr uint32_t STAGE_BYTES = 32768;
static constexpr uint32_t SMEM_ASK = STAGES * STAGE_BYTES + 2048;

static constexpr int CONV_CTAS = 128;   // per expert
static constexpr int G1_CTAS = 256;     // per expert
static constexpr int EXP_CTAS = CONV_CTAS + G1_CTAS;

__global__ void zero_flags() {
    if (threadIdx.x < NE) g_flag[threadIdx.x] = 0;
}

// ============================================================================
// GEMM1 (+ fused converters): grid = NE * (128 conv + 256 gemm) CTAs.
// Conv CTAs: convert X(e), W1(e) fp32 -> fp16, release flag[e], exit.
// GEMM CTAs: convert W2 slice (useful work), spin on flag[e], then mainloop.
// ============================================================================
__global__ void __launch_bounds__(128, 2) moe_gemm1(
    const __grid_constant__ CUtensorMap tmA,
    const __grid_constant__ CUtensorMap tmB,
    const float4* __restrict__ w2src,
    const float4* __restrict__ xsrc,
    const float4* __restrict__ w1src) {
    extern __shared__ __align__(16) char dsm[];
    int tid = threadIdx.x;
    int b = blockIdx.x;
    int e = b / EXP_CTAS;
    int sub = b - e * EXP_CTAS;

    if (sub < CONV_CTAS) {
        // --- converter CTA: X slice + W1 slice of expert e ---
        {
            const float4* src = xsrc + (size_t)e * (NT * NH / 4) + (size_t)sub * 2048;
            uint2* dst = reinterpret_cast<uint2*>(g_xh) + (size_t)e * (NT * NH / 4) + (size_t)sub * 2048;
            #pragma unroll 4
            for (int i = tid; i < 2048; i += 128) {
                float4 v = src[i];
                uint2 o;
                o.x = pack_h2(v.x, v.y);
                o.y = pack_h2(v.z, v.w);
                dst[i] = o;
            }
        }
        {
            const float4* src = w1src + (size_t)e * (2 * NI * NH / 4) + (size_t)sub * 32768;
            uint2* dst = reinterpret_cast<uint2*>(g_w1h) + (size_t)e * (2 * NI * NH / 4) + (size_t)sub * 32768;
            #pragma unroll 4
            for (int i = tid; i < 32768; i += 128) {
                float4 v = src[i];
                uint2 o;
                o.x = pack_h2(v.x, v.y);
                o.y = pack_h2(v.z, v.w);
                dst[i] = o;
            }
        }
        __threadfence();
        __syncthreads();
        if (tid == 0) atomicAdd(&g_flag[e], 1);
        return;
    }

    // --- gemm CTA ---
    int g1 = sub - CONV_CTAS;            // 0..255
    int mt = g1 & 3, nt = (g1 >> 2) & 63;
    int arow = e * NT + mt * 128;
    int grow = e * (2 * NI) + nt * 64;
    int urow = grow + NI;

    uint32_t base = (smem_u32(dsm) + 1023u) & ~1023u;
    uint32_t fullb = base + STAGES * STAGE_BYTES;
    uint32_t emptb = fullb + 64;

    int wid = tid >> 5, lane = tid & 31;
    int g = lane >> 2, tig = lane & 3;
    int wm = wid >> 1, wn = wid & 1;
    uint32_t xr = (uint32_t)g << 4;

    if (tid == 0) {
        for (uint32_t s = 0; s < STAGES; s++) { MBAR_INIT(fullb + 8 * s, 1); MBAR_INIT(emptb + 8 * s, 4); }
        asm volatile("fence.proxy.async.shared::cta;" ::: "memory");
    }
    __syncthreads();

    // W2 conversion slice (useful work while waiting on conv CTAs)
    {
        int o = e * G1_CTAS + g1;        // 0..4095
        const float4* src = w2src + (size_t)o * 8192;
        uint2* dst = reinterpret_cast<uint2*>(g_w2h) + (size_t)o * 8192;
        #pragma unroll 4
        for (int i = tid; i < 8192; i += 128) {
            float4 v = src[i];
            uint2 o2;
            o2.x = pack_h2(v.x, v.y);
            o2.y = pack_h2(v.z, v.w);
            dst[i] = o2;
        }
    }

    // wait for this expert's X/W1 conversion
    if (tid == 0) {
        while (acq_ld(&g_flag[e]) < CONV_CTAS) __nanosleep(200);
    }
    __syncthreads();

    if (tid == 0) {
        for (uint32_t c = 0; c < STAGES; c++) {
            uint32_t sb = base + c * STAGE_BYTES;
            MBAR_EXPECT_TX(fullb + 8 * c, STAGE_BYTES);
            TMA2D(sb,         &tmA, (int)c * 64, arow, fullb + 8 * c);
            TMA2D(sb + 16384, &tmB, (int)c * 64, grow, fullb + 8 * c);
            TMA2D(sb + 24576, &tmB, (int)c * 64, urow, fullb + 8 * c);
        }
    }

    float accg[4][4][4], accu[4][4][4];
    #pragma unroll
    for (int i = 0; i < 4; i++)
        #pragma unroll
        for (int j = 0; j < 4; j++)
            #pragma unroll
            for (int q = 0; q < 4; q++) { accg[i][j][q] = 0.f; accu[i][j][q] = 0.f; }

    uint32_t rowA[4];
    #pragma unroll
    for (int mi = 0; mi < 4; mi++) rowA[mi] = (uint32_t)(wm * 64 + mi * 16 + g) * 128;
    uint32_t rowB = (uint32_t)(wn * 32 + g) * 128;

    uint32_t C0[4], C1[4];
    #pragma unroll
    for (int kk = 0; kk < 4; kk++) {
        C0[kk] = ((uint32_t)(kk * 32 + tig * 4)) ^ xr;
        C1[kk] = ((uint32_t)(kk * 32 + 16 + tig * 4)) ^ xr;
    }

    uint32_t Af[2][16], Bg[2][2], Bu[2][2];

    #define LDA4g(buf, sA, kk, mi) do {                                          \
        Af[buf][(mi) * 4 + 0] = lds_u32((sA) + rowA[mi] + C0[kk]);               \
        Af[buf][(mi) * 4 + 1] = lds_u32((sA) + rowA[mi] + 1024 + C0[kk]);        \
        Af[buf][(mi) * 4 + 2] = lds_u32((sA) + rowA[mi] + C1[kk]);               \
        Af[buf][(mi) * 4 + 3] = lds_u32((sA) + rowA[mi] + 1024 + C1[kk]);        \
    } while (0)
    #define LDGU(buf, sA, kk, nj) do {                                           \
        uint32_t _o = rowB + (uint32_t)(nj) * 1024;                              \
        Bg[buf][0] = lds_u32((sA) + 16384 + _o + C0[kk]);                        \
        Bg[buf][1] = lds_u32((sA) + 16384 + _o + C1[kk]);                        \
        Bu[buf][0] = lds_u32((sA) + 24576 + _o + C0[kk]);                        \
        Bu[buf][1] = lds_u32((sA) + 24576 + _o + C1[kk]);                        \
    } while (0)

    int s = 0, ph = 0;
    #pragma unroll 1
    for (int ks = 0; ks < 32; ks++) {
        WAIT_PAR(fullb + 8 * s, ph);
        uint32_t sA = base + (uint32_t)s * STAGE_BYTES;
        OPAQUE(sA);

        #pragma unroll
        for (int mi = 0; mi < 4; mi++) LDA4g(0, sA, 0, mi);
        LDGU(0, sA, 0, 0);

        #pragma unroll
        for (int kk = 0; kk < 4; kk++) {
            #pragma unroll
            for (int nj = 0; nj < 4; nj++) {
                int grp = kk * 4 + nj;
                int cb = grp & 1;
                if (nj < 3)       LDGU(cb ^ 1, sA, kk, nj + 1);
                else if (kk < 3)  LDGU(cb ^ 1, sA, kk + 1, 0);
                if (kk < 3) LDA4g((kk + 1) & 1, sA, kk + 1, nj);
                int ab = kk & 1;
                #pragma unroll
                for (int mi = 0; mi < 4; mi++) {
                    MMA_F16(accg[mi][nj], Af[ab][mi * 4 + 0], Af[ab][mi * 4 + 1],
                            Af[ab][mi * 4 + 2], Af[ab][mi * 4 + 3],
                            Bg[cb][0], Bg[cb][1]);
                    MMA_F16(accu[mi][nj], Af[ab][mi * 4 + 0], Af[ab][mi * 4 + 1],
                            Af[ab][mi * 4 + 2], Af[ab][mi * 4 + 3],
                            Bu[cb][0], Bu[cb][1]);
                }
            }
        }
        if (lane == 0) MBAR_ARRIVE(emptb + 8 * s);
        if (tid == 0 && ks + (int)STAGES < 32) {
            WAIT_PAR(emptb + 8 * s, ph);
            uint32_t sb = base + (uint32_t)s * STAGE_BYTES;
            MBAR_EXPECT_TX(fullb + 8 * s, STAGE_BYTES);
            TMA2D(sb,         &tmA, (ks + (int)STAGES) * 64, arow, fullb + 8 * s);
            TMA2D(sb + 16384, &tmB, (ks + (int)STAGES) * 64, grow, fullb + 8 * s);
            TMA2D(sb + 24576, &tmB, (ks + (int)STAGES) * 64, urow, fullb + 8 * s);
        }
        if (++s == (int)STAGES) { s = 0; ph ^= 1; }
    }
    #undef LDA4g
    #undef LDGU

    // Epilogue: SwiGLU -> fp16 act
    #pragma unroll
    for (int mi = 0; mi < 4; mi++) {
        int tok0 = mt * 128 + wm * 64 + mi * 16 + g;
        __half* p0 = g_act_h + (size_t)(e * NT + tok0) * NI + nt * 64 + wn * 32;
        __half* p1 = p0 + (size_t)8 * NI;
        #pragma unroll
        for (int nj = 0; nj < 4; nj++) {
            int colo = nj * 8 + 2 * tig;
            float v00, v01, v10, v11;
            float gg = accg[mi][nj][0], uu = accu[mi][nj][0];
            v00 = uu * gg / (1.0f + __expf(-gg));
            gg = accg[mi][nj][1]; uu = accu[mi][nj][1];
            v01 = uu * gg / (1.0f + __expf(-gg));
            gg = accg[mi][nj][2]; uu = accu[mi][nj][2];
            v10 = uu * gg / (1.0f + __expf(-gg));
            gg = accg[mi][nj][3]; uu = accu[mi][nj][3];
            v11 = uu * gg / (1.0f + __expf(-gg));
            *reinterpret_cast<uint32_t*>(p0 + colo) = pack_h2(v00, v01);
            *reinterpret_cast<uint32_t*>(p1 + colo) = pack_h2(v10, v11);
        }
    }
}

// ============================================================================
// GEMM2: out = act @ W2^T. CTA 128x128, 4 warps, warp tile 64x64, 2 CTAs/SM.
// ============================================================================
__global__ void __launch_bounds__(128, 2) moe_gemm2(
    const __grid_constant__ CUtensorMap tmA,
    const __grid_constant__ CUtensorMap tmB,
    float* __restrict__ out) {
    extern __shared__ __align__(16) char dsm[];
    uint32_t base = (smem_u32(dsm) + 1023u) & ~1023u;
    uint32_t fullb = base + STAGES * STAGE_BYTES;
    uint32_t emptb = fullb + 64;

    int tid = threadIdx.x, wid = tid >> 5, lane = tid & 31;
    int g = lane >> 2, tig = lane & 3;
    int wm = wid >> 1, wn = wid & 1;
    uint32_t xr = (uint32_t)g << 4;

    int b = blockIdx.x;
    int mt = b & 3, nt = (b >> 2) & 15, e = b >> 6;
    int arow = e * NT + mt * 128;
    int brow = e * NH + nt * 128;

    if (tid == 0) {
        for (uint32_t s = 0; s < STAGES; s++) { MBAR_INIT(fullb + 8 * s, 1); MBAR_INIT(emptb + 8 * s, 4); }
        asm volatile("fence.proxy.async.shared::cta;" ::: "memory");
    }
    __syncthreads();

    if (tid == 0) {
        for (uint32_t c = 0; c < STAGES; c++) {
            uint32_t sb = base + c * STAGE_BYTES;
            MBAR_EXPECT_TX(fullb + 8 * c, STAGE_BYTES);
            TMA2D(sb,         &tmA, (int)c * 64, arow, fullb + 8 * c);
            TMA2D(sb + 16384, &tmB, (int)c * 64, brow, fullb + 8 * c);
        }
    }

    float acc[4][8][4];
    #pragma unroll
    for (int i = 0; i < 4; i++)
        #pragma unroll
        for (int j = 0; j < 8; j++)
            #pragma unroll
            for (int q = 0; q < 4; q++) acc[i][j][q] = 0.f;

    uint32_t rowA[4];
    #pragma unroll
    for (int mi = 0; mi < 4; mi++) rowA[mi] = (uint32_t)(wm * 64 + mi * 16 + g) * 128;
    uint32_t rowB = (uint32_t)(wn * 64 + g) * 128;

    uint32_t C0[4], C1[4];
    #pragma unroll
    for (int kk = 0; kk < 4; kk++) {
        C0[kk] = ((uint32_t)(kk * 32 + tig * 4)) ^ xr;
        C1[kk] = ((uint32_t)(kk * 32 + 16 + tig * 4)) ^ xr;
    }

    uint32_t Af[2][16], Bf[2][2];

    #define LDA4(buf, sA, kk, mi) do {                                           \
        Af[buf][(mi) * 4 + 0] = lds_u32((sA) + rowA[mi] + C0[kk]);               \
        Af[buf][(mi) * 4 + 1] = lds_u32((sA) + rowA[mi] + 1024 + C0[kk]);        \
        Af[buf][(mi) * 4 + 2] = lds_u32((sA) + rowA[mi] + C1[kk]);               \
        Af[buf][(mi) * 4 + 3] = lds_u32((sA) + rowA[mi] + 1024 + C1[kk]);        \
    } while (0)
    #define LDB2(buf, sB, kk, nj) do {                                           \
        Bf[buf][0] = lds_u32((sB) + rowB + (uint32_t)(nj) * 1024 + C0[kk]);      \
        Bf[buf][1] = lds_u32((sB) + rowB + (uint32_t)(nj) * 1024 + C1[kk]);      \
    } while (0)

    int s = 0, ph = 0;
    #pragma unroll 1
    for (int ks = 0; ks < 64; ks++) {
        WAIT_PAR(fullb + 8 * s, ph);
        uint32_t sA = base + (uint32_t)s * STAGE_BYTES;
        OPAQUE(sA);
        uint32_t sB = sA + 16384;

        #pragma unroll
        for (int mi = 0; mi < 4; mi++) LDA4(0, sA, 0, mi);
        LDB2(0, sB, 0, 0);

        #pragma unroll
        for (int kk = 0; kk < 4; kk++) {
            #pragma unroll
            for (int nj = 0; nj < 8; nj++) {
                int grp = kk * 8 + nj;
                int cb = grp & 1;
                if (nj < 7)       LDB2(cb ^ 1, sB, kk, nj + 1);
                else if (kk < 3)  LDB2(cb ^ 1, sB, kk + 1, 0);
                if (kk < 3 && nj >= 4) LDA4((kk + 1) & 1, sA, kk + 1, nj - 4);
                int ab = kk & 1;
                #pragma unroll
                for (int mi = 0; mi < 4; mi++)
                    MMA_F16(acc[mi][nj], Af[ab][mi * 4 + 0], Af[ab][mi * 4 + 1],
                            Af[ab][mi * 4 + 2], Af[ab][mi * 4 + 3],
                            Bf[cb][0], Bf[cb][1]);
            }
        }
        if (lane == 0) MBAR_ARRIVE(emptb + 8 * s);
        if (tid == 0 && ks + (int)STAGES < 64) {
            WAIT_PAR(emptb + 8 * s, ph);
            uint32_t sb = base + (uint32_t)s * STAGE_BYTES;
            MBAR_EXPECT_TX(fullb + 8 * s, STAGE_BYTES);
            TMA2D(sb,         &tmA, (ks + (int)STAGES) * 64, arow, fullb + 8 * s);
            TMA2D(sb + 16384, &tmB, (ks + (int)STAGES) * 64, brow, fullb + 8 * s);
        }
        if (++s == (int)STAGES) { s = 0; ph ^= 1; }
    }
    #undef LDA4
    #undef LDB2

    #pragma unroll
    for (int mi = 0; mi < 4; mi++) {
        int tok0 = mt * 128 + wm * 64 + mi * 16 + g;
        float* p0 = out + (size_t)(e * NT + tok0) * NH + nt * 128 + wn * 64;
        float* p1 = p0 + (size_t)8 * NH;
        #pragma unroll
        for (int nj = 0; nj < 8; nj++) {
            int colo = nj * 8 + 2 * tig;
            float2 v0 = {acc[mi][nj][0], acc[mi][nj][1]};
            float2 v1 = {acc[mi][nj][2], acc[mi][nj][3]};
            *reinterpret_cast<float2*>(p0 + colo) = v0;
            *reinterpret_cast<float2*>(p1 + colo) = v1;
        }
    }
}

// ============================================================================
// Host
// ============================================================================
typedef CUresult (*EncodeFn)(CUtensorMap*, CUtensorMapDataType, cuuint32_t, void*,
                             const cuuint64_t*, const cuuint64_t*, const cuuint32_t*,
                             const cuuint32_t*, CUtensorMapInterleave, CUtensorMapSwizzle,
                             CUtensorMapL2promotion, CUtensorMapFloatOOBfill);

static void encode2d_h(EncodeFn fn, CUtensorMap* m, void* p,
                       uint64_t d0, uint64_t d1, uint64_t stride_bytes,
                       uint32_t b0, uint32_t b1) {
    cuuint64_t dims[2] = {d0, d1};
    cuuint64_t st[1]   = {stride_bytes};
    cuuint32_t box[2]  = {b0, b1};
    cuuint32_t es[2]   = {1, 1};
    fn(m, CU_TENSOR_MAP_DATA_TYPE_FLOAT16, 2, p, dims, st, box, es,
       CU_TENSOR_MAP_INTERLEAVE_NONE, CU_TENSOR_MAP_SWIZZLE_128B,
       CU_TENSOR_MAP_L2_PROMOTION_L2_128B, CU_TENSOR_MAP_FLOAT_OOB_FILL_NONE);
}

extern "C" void kernel_launch(void* const* d_in, const int* in_sizes, int n_in,
                              void* d_out, int out_size) {
    void* X  = d_in[0];  // (E*T, H) fp32
    void* W1 = d_in[1];  // (E, 2I, H) fp32
    void* W2 = d_in[2];  // (E, H, I) fp32

    void* pfn = nullptr;
    cudaDriverEntryPointQueryResult qr;
#if CUDART_VERSION >= 12050
    cudaGetDriverEntryPointByVersion("cuTensorMapEncodeTiled", &pfn, 12000,
                                     cudaEnableDefault, &qr);
#else
    cudaGetDriverEntryPoint("cuTensorMapEncodeTiled", &pfn, cudaEnableDefault, &qr);
#endif
    EncodeFn enc = (EncodeFn)pfn;

    void *xh, *w1h, *w2h, *acth;
    cudaGetSymbolAddress(&xh,  g_xh);
    cudaGetSymbolAddress(&w1h, g_w1h);
    cudaGetSymbolAddress(&w2h, g_w2h);
    cudaGetSymbolAddress(&acth, g_act_h);

    CUtensorMap tA, tB, tA2, tB2;
    encode2d_h(enc, &tA,  xh,   NH, (uint64_t)NE * NT,     (uint64_t)NH * 2, 64, 128);
    encode2d_h(enc, &tB,  w1h,  NH, (uint64_t)NE * 2 * NI, (uint64_t)NH * 2, 64, 64);
    encode2d_h(enc, &tA2, acth, NI, (uint64_t)NE * NT,     (uint64_t)NI * 2, 64, 128);
    encode2d_h(enc, &tB2, w2h,  NI, (uint64_t)NE * NH,     (uint64_t)NI * 2, 64, 128);

    cudaFuncSetAttribute(moe_gemm1, cudaFuncAttributeMaxDynamicSharedMemorySize, SMEM_ASK);
    cudaFuncSetAttribute(moe_gemm2, cudaFuncAttributeMaxDynamicSharedMemorySize, SMEM_ASK);

    zero_flags<<<1, 32>>>();
    moe_gemm1<<<NE * EXP_CTAS, 128, SMEM_ASK>>>(tA, tB, (const float4*)W2,
                                                (const float4*)X, (const float4*)W1);
    moe_gemm2<<<NE * 4 * 16, 128, SMEM_ASK>>>(tA2, tB2, (float*)d_out);
}

// round 12
// speedup vs baseline: 1.3652x; 1.3652x over previous
#include <cuda_runtime.h>
#include <cuda.h>
#include <cuda_fp16.h>
#include <cstdint>

#define NE 16
#define NT 512
#define NH 2048
#define NI 4096

// scratch (allocation-free rule: __device__ globals)
__device__ __align__(1024) __half g_act_h[(size_t)NE * NT * NI];      // 67MB
__device__ __align__(1024) __half g_xh[(size_t)NE * NT * NH];         // 34MB
__device__ __align__(1024) __half g_w1h[(size_t)NE * 2 * NI * NH];    // 537MB
__device__ __align__(1024) __half g_w2h[(size_t)NE * NH * NI];        // 268MB

// ---------------- device helpers ----------------
__device__ __forceinline__ uint32_t smem_u32(const void* p) {
    uint32_t a;
    asm("{ .reg .u64 t; cvta.to.shared.u64 t, %1; cvt.u32.u64 %0, t; }" : "=r"(a) : "l"(p));
    return a;
}

#define MBAR_INIT(addr, cnt) \
    asm volatile("mbarrier.init.shared.b64 [%0], %1;" :: "r"(addr), "r"(cnt) : "memory")
#define MBAR_EXPECT_TX(addr, bytes) \
    asm volatile("mbarrier.arrive.expect_tx.shared.b64 _, [%0], %1;" :: "r"(addr), "r"(bytes) : "memory")
#define MBAR_ARRIVE(addr) \
    asm volatile("mbarrier.arrive.shared.b64 _, [%0];" :: "r"(addr) : "memory")
#define WAIT_PAR(addr, ph) do {                                                  \
    uint32_t _a = (addr), _p = (ph);                                             \
    asm volatile("{\n\t.reg .pred P;\n\t"                                        \
                 "WL_%=:\n\t"                                                    \
                 "mbarrier.try_wait.parity.shared.b64 P, [%0], %1, 0x989680;\n\t"\
                 "@!P bra WL_%=;\n\t}" :: "r"(_a), "r"(_p) : "memory");          \
} while (0)

#define OPAQUE(x) asm volatile("" : "+r"(x))

#define TMA2D(smem, map, x, y, mbar)                                                          \
    asm volatile("cp.async.bulk.tensor.2d.shared::cta.global.tile.mbarrier::complete_tx::bytes " \
                 "[%0], [%1, {%2, %3}], [%4];"                                                \
                 :: "r"(smem), "l"(map), "r"(x), "r"(y), "r"(mbar) : "memory")

__device__ __forceinline__ uint32_t lds_u32(uint32_t addr) {
    uint32_t v;
    asm("ld.shared.b32 %0, [%1];" : "=r"(v) : "r"(addr));
    return v;
}

__device__ __forceinline__ uint32_t pack_h2(float lo, float hi) {
    uint32_t r;
    asm("{\n\t.reg .b16 a, b;\n\tcvt.rn.f16.f32 a, %1;\n\tcvt.rn.f16.f32 b, %2;\n\t"
        "mov.b32 %0, {a, b};\n\t}" : "=r"(r) : "f"(lo), "f"(hi));
    return r;
}

#define MMA_F16(c, a0, a1, a2, a3, b0, b1)                                       \
    asm volatile("mma.sync.aligned.m16n8k16.row.col.f32.f16.f16.f32 "            \
                 "{%0,%1,%2,%3}, {%4,%5,%6,%7}, {%8,%9}, {%0,%1,%2,%3};"         \
                 : "+f"((c)[0]), "+f"((c)[1]), "+f"((c)[2]), "+f"((c)[3])        \
                 : "r"(a0), "r"(a1), "r"(a2), "r"(a3), "r"(b0), "r"(b1))

static constexpr uint32_t STAGES = 3;
static constexpr uint32_t STAGE_BYTES = 32768;
static constexpr uint32_t SMEM_ASK = STAGES * STAGE_BYTES + 2048;

// ============================================================================
// conv chunk: convert X(e0:e1) and W1(e0:e1) fp32 -> fp16 (runs on stream s1)
// ============================================================================
__global__ void conv_chunk(const float4* __restrict__ xsrc,
                           const float4* __restrict__ w1src,
                           int e0, int e1) {
    size_t w1n4 = (size_t)(e1 - e0) * (2 * NI * NH / 4);
    size_t xn4  = (size_t)(e1 - e0) * (NT * NH / 4);
    const float4* w1s = w1src + (size_t)e0 * (2 * NI * NH / 4);
    uint2* w1d = reinterpret_cast<uint2*>(g_w1h) + (size_t)e0 * (2 * NI * NH / 4);
    const float4* xs = xsrc + (size_t)e0 * (NT * NH / 4);
    uint2* xd = reinterpret_cast<uint2*>(g_xh) + (size_t)e0 * (NT * NH / 4);

    size_t total = w1n4 + xn4;
    size_t stride = (size_t)gridDim.x * blockDim.x;
    for (size_t i = (size_t)blockIdx.x * blockDim.x + threadIdx.x; i < total; i += stride) {
        float4 v;
        uint2* dp;
        if (i < w1n4) { v = w1s[i]; dp = w1d + i; }
        else          { v = xs[i - w1n4]; dp = xd + (i - w1n4); }
        uint2 o;
        o.x = pack_h2(v.x, v.y);
        o.y = pack_h2(v.z, v.w);
        *dp = o;
    }
}

// ============================================================================
// GEMM1 chunk: experts [e0, e0 + grid/256). CTA 128 tok x 64 act-cols, 4 warps,
// warp tile 64 x (32g + 32u), 2 CTAs/SM. W2-conv slice in preamble.
// ============================================================================
__global__ void __launch_bounds__(128, 2) moe_gemm1(
    const __grid_constant__ CUtensorMap tmA,
    const __grid_constant__ CUtensorMap tmB,
    const float4* __restrict__ w2src,
    int e0) {
    extern __shared__ __align__(16) char dsm[];
    int tid = threadIdx.x;
    int b = blockIdx.x;
    int e = e0 + (b >> 8);
    int g1 = b & 255;
    int mt = g1 & 3, nt = (g1 >> 2) & 63;
    int arow = e * NT + mt * 128;
    int grow = e * (2 * NI) + nt * 64;
    int urow = grow + NI;

    uint32_t base = (smem_u32(dsm) + 1023u) & ~1023u;
    uint32_t fullb = base + STAGES * STAGE_BYTES;
    uint32_t emptb = fullb + 64;

    int wid = tid >> 5, lane = tid & 31;
    int g = lane >> 2, tig = lane & 3;
    int wm = wid >> 1, wn = wid & 1;
    uint32_t xr = (uint32_t)g << 4;

    if (tid == 0) {
        for (uint32_t s = 0; s < STAGES; s++) { MBAR_INIT(fullb + 8 * s, 1); MBAR_INIT(emptb + 8 * s, 4); }
        asm volatile("fence.proxy.async.shared::cta;" ::: "memory");
    }
    __syncthreads();

    if (tid == 0) {
        for (uint32_t c = 0; c < STAGES; c++) {
            uint32_t sb = base + c * STAGE_BYTES;
            MBAR_EXPECT_TX(fullb + 8 * c, STAGE_BYTES);
            TMA2D(sb,         &tmA, (int)c * 64, arow, fullb + 8 * c);
            TMA2D(sb + 16384, &tmB, (int)c * 64, grow, fullb + 8 * c);
            TMA2D(sb + 24576, &tmB, (int)c * 64, urow, fullb + 8 * c);
        }
    }

    // W2 conversion slice (overlaps the TMA pipeline fill + early mainloop)
    {
        int o = e * 256 + g1;            // 0..4095 over all chunks
        const float4* src = w2src + (size_t)o * 8192;
        uint2* dst = reinterpret_cast<uint2*>(g_w2h) + (size_t)o * 8192;
        #pragma unroll 4
        for (int i = tid; i < 8192; i += 128) {
            float4 v = src[i];
            uint2 o2;
            o2.x = pack_h2(v.x, v.y);
            o2.y = pack_h2(v.z, v.w);
            dst[i] = o2;
        }
    }

    float accg[4][4][4], accu[4][4][4];
    #pragma unroll
    for (int i = 0; i < 4; i++)
        #pragma unroll
        for (int j = 0; j < 4; j++)
            #pragma unroll
            for (int q = 0; q < 4; q++) { accg[i][j][q] = 0.f; accu[i][j][q] = 0.f; }

    uint32_t rowA[4];
    #pragma unroll
    for (int mi = 0; mi < 4; mi++) rowA[mi] = (uint32_t)(wm * 64 + mi * 16 + g) * 128;
    uint32_t rowB = (uint32_t)(wn * 32 + g) * 128;

    uint32_t C0[4], C1[4];
    #pragma unroll
    for (int kk = 0; kk < 4; kk++) {
        C0[kk] = ((uint32_t)(kk * 32 + tig * 4)) ^ xr;
        C1[kk] = ((uint32_t)(kk * 32 + 16 + tig * 4)) ^ xr;
    }

    uint32_t Af[2][16], Bg[2][2], Bu[2][2];

    #define LDA4g(buf, sA, kk, mi) do {                                          \
        Af[buf][(mi) * 4 + 0] = lds_u32((sA) + rowA[mi] + C0[kk]);               \
        Af[buf][(mi) * 4 + 1] = lds_u32((sA) + rowA[mi] + 1024 + C0[kk]);        \
        Af[buf][(mi) * 4 + 2] = lds_u32((sA) + rowA[mi] + C1[kk]);               \
        Af[buf][(mi) * 4 + 3] = lds_u32((sA) + rowA[mi] + 1024 + C1[kk]);        \
    } while (0)
    #define LDGU(buf, sA, kk, nj) do {                                           \
        uint32_t _o = rowB + (uint32_t)(nj) * 1024;                              \
        Bg[buf][0] = lds_u32((sA) + 16384 + _o + C0[kk]);                        \
        Bg[buf][1] = lds_u32((sA) + 16384 + _o + C1[kk]);                        \
        Bu[buf][0] = lds_u32((sA) + 24576 + _o + C0[kk]);                        \
        Bu[buf][1] = lds_u32((sA) + 24576 + _o + C1[kk]);                        \
    } while (0)

    int s = 0, ph = 0;
    #pragma unroll 1
    for (int ks = 0; ks < 32; ks++) {
        WAIT_PAR(fullb + 8 * s, ph);
        uint32_t sA = base + (uint32_t)s * STAGE_BYTES;
        OPAQUE(sA);

        #pragma unroll
        for (int mi = 0; mi < 4; mi++) LDA4g(0, sA, 0, mi);
        LDGU(0, sA, 0, 0);

        #pragma unroll
        for (int kk = 0; kk < 4; kk++) {
            #pragma unroll
            for (int nj = 0; nj < 4; nj++) {
                int grp = kk * 4 + nj;
                int cb = grp & 1;
                if (nj < 3)       LDGU(cb ^ 1, sA, kk, nj + 1);
                else if (kk < 3)  LDGU(cb ^ 1, sA, kk + 1, 0);
                if (kk < 3) LDA4g((kk + 1) & 1, sA, kk + 1, nj);
                int ab = kk & 1;
                #pragma unroll
                for (int mi = 0; mi < 4; mi++) {
                    MMA_F16(accg[mi][nj], Af[ab][mi * 4 + 0], Af[ab][mi * 4 + 1],
                            Af[ab][mi * 4 + 2], Af[ab][mi * 4 + 3],
                            Bg[cb][0], Bg[cb][1]);
                    MMA_F16(accu[mi][nj], Af[ab][mi * 4 + 0], Af[ab][mi * 4 + 1],
                            Af[ab][mi * 4 + 2], Af[ab][mi * 4 + 3],
                            Bu[cb][0], Bu[cb][1]);
                }
            }
        }
        if (lane == 0) MBAR_ARRIVE(emptb + 8 * s);
        if (tid == 0 && ks + (int)STAGES < 32) {
            WAIT_PAR(emptb + 8 * s, ph);
            uint32_t sb = base + (uint32_t)s * STAGE_BYTES;
            MBAR_EXPECT_TX(fullb + 8 * s, STAGE_BYTES);
            TMA2D(sb,         &tmA, (ks + (int)STAGES) * 64, arow, fullb + 8 * s);
            TMA2D(sb + 16384, &tmB, (ks + (int)STAGES) * 64, grow, fullb + 8 * s);
            TMA2D(sb + 24576, &tmB, (ks + (int)STAGES) * 64, urow, fullb + 8 * s);
        }
        if (++s == (int)STAGES) { s = 0; ph ^= 1; }
    }
    #undef LDA4g
    #undef LDGU

    // Epilogue: SwiGLU -> fp16 act
    #pragma unroll
    for (int mi = 0; mi < 4; mi++) {
        int tok0 = mt * 128 + wm * 64 + mi * 16 + g;
        __half* p0 = g_act_h + (size_t)(e * NT + tok0) * NI + nt * 64 + wn * 32;
        __half* p1 = p0 + (size_t)8 * NI;
        #pragma unroll
        for (int nj = 0; nj < 4; nj++) {
            int colo = nj * 8 + 2 * tig;
            float v00, v01, v10, v11;
            float gg = accg[mi][nj][0], uu = accu[mi][nj][0];
            v00 = uu * gg / (1.0f + __expf(-gg));
            gg = accg[mi][nj][1]; uu = accu[mi][nj][1];
            v01 = uu * gg / (1.0f + __expf(-gg));
            gg = accg[mi][nj][2]; uu = accu[mi][nj][2];
            v10 = uu * gg / (1.0f + __expf(-gg));
            gg = accg[mi][nj][3]; uu = accu[mi][nj][3];
            v11 = uu * gg / (1.0f + __expf(-gg));
            *reinterpret_cast<uint32_t*>(p0 + colo) = pack_h2(v00, v01);
            *reinterpret_cast<uint32_t*>(p1 + colo) = pack_h2(v10, v11);
        }
    }
}

// ============================================================================
// GEMM2: out = act @ W2^T. CTA 128x128, 4 warps, warp tile 64x64, 2 CTAs/SM.
// ============================================================================
__global__ void __launch_bounds__(128, 2) moe_gemm2(
    const __grid_constant__ CUtensorMap tmA,
    const __grid_constant__ CUtensorMap tmB,
    float* __restrict__ out) {
    extern __shared__ __align__(16) char dsm[];
    uint32_t base = (smem_u32(dsm) + 1023u) & ~1023u;
    uint32_t fullb = base + STAGES * STAGE_BYTES;
    uint32_t emptb = fullb + 64;

    int tid = threadIdx.x, wid = tid >> 5, lane = tid & 31;
    int g = lane >> 2, tig = lane & 3;
    int wm = wid >> 1, wn = wid & 1;
    uint32_t xr = (uint32_t)g << 4;

    int b = blockIdx.x;
    int mt = b & 3, nt = (b >> 2) & 15, e = b >> 6;
    int arow = e * NT + mt * 128;
    int brow = e * NH + nt * 128;

    if (tid == 0) {
        for (uint32_t s = 0; s < STAGES; s++) { MBAR_INIT(fullb + 8 * s, 1); MBAR_INIT(emptb + 8 * s, 4); }
        asm volatile("fence.proxy.async.shared::cta;" ::: "memory");
    }
    __syncthreads();

    if (tid == 0) {
        for (uint32_t c = 0; c < STAGES; c++) {
            uint32_t sb = base + c * STAGE_BYTES;
            MBAR_EXPECT_TX(fullb + 8 * c, STAGE_BYTES);
            TMA2D(sb,         &tmA, (int)c * 64, arow, fullb + 8 * c);
            TMA2D(sb + 16384, &tmB, (int)c * 64, brow, fullb + 8 * c);
        }
    }

    float acc[4][8][4];
    #pragma unroll
    for (int i = 0; i < 4; i++)
        #pragma unroll
        for (int j = 0; j < 8; j++)
            #pragma unroll
            for (int q = 0; q < 4; q++) acc[i][j][q] = 0.f;

    uint32_t rowA[4];
    #pragma unroll
    for (int mi = 0; mi < 4; mi++) rowA[mi] = (uint32_t)(wm * 64 + mi * 16 + g) * 128;
    uint32_t rowB = (uint32_t)(wn * 64 + g) * 128;

    uint32_t C0[4], C1[4];
    #pragma unroll
    for (int kk = 0; kk < 4; kk++) {
        C0[kk] = ((uint32_t)(kk * 32 + tig * 4)) ^ xr;
        C1[kk] = ((uint32_t)(kk * 32 + 16 + tig * 4)) ^ xr;
    }

    uint32_t Af[2][16], Bf[2][2];

    #define LDA4(buf, sA, kk, mi) do {                                           \
        Af[buf][(mi) * 4 + 0] = lds_u32((sA) + rowA[mi] + C0[kk]);               \
        Af[buf][(mi) * 4 + 1] = lds_u32((sA) + rowA[mi] + 1024 + C0[kk]);        \
        Af[buf][(mi) * 4 + 2] = lds_u32((sA) + rowA[mi] + C1[kk]);               \
        Af[buf][(mi) * 4 + 3] = lds_u32((sA) + rowA[mi] + 1024 + C1[kk]);        \
    } while (0)
    #define LDB2(buf, sB, kk, nj) do {                                           \
        Bf[buf][0] = lds_u32((sB) + rowB + (uint32_t)(nj) * 1024 + C0[kk]);      \
        Bf[buf][1] = lds_u32((sB) + rowB + (uint32_t)(nj) * 1024 + C1[kk]);      \
    } while (0)

    int s = 0, ph = 0;
    #pragma unroll 1
    for (int ks = 0; ks < 64; ks++) {
        WAIT_PAR(fullb + 8 * s, ph);
        uint32_t sA = base + (uint32_t)s * STAGE_BYTES;
        OPAQUE(sA);
        uint32_t sB = sA + 16384;

        #pragma unroll
        for (int mi = 0; mi < 4; mi++) LDA4(0, sA, 0, mi);
        LDB2(0, sB, 0, 0);

        #pragma unroll
        for (int kk = 0; kk < 4; kk++) {
            #pragma unroll
            for (int nj = 0; nj < 8; nj++) {
                int grp = kk * 8 + nj;
                int cb = grp & 1;
                if (nj < 7)       LDB2(cb ^ 1, sB, kk, nj + 1);
                else if (kk < 3)  LDB2(cb ^ 1, sB, kk + 1, 0);
                if (kk < 3 && nj >= 4) LDA4((kk + 1) & 1, sA, kk + 1, nj - 4);
                int ab = kk & 1;
                #pragma unroll
                for (int mi = 0; mi < 4; mi++)
                    MMA_F16(acc[mi][nj], Af[ab][mi * 4 + 0], Af[ab][mi * 4 + 1],
                            Af[ab][mi * 4 + 2], Af[ab][mi * 4 + 3],
                            Bf[cb][0], Bf[cb][1]);
            }
        }
        if (lane == 0) MBAR_ARRIVE(emptb + 8 * s);
        if (tid == 0 && ks + (int)STAGES < 64) {
            WAIT_PAR(emptb + 8 * s, ph);
            uint32_t sb = base + (uint32_t)s * STAGE_BYTES;
            MBAR_EXPECT_TX(fullb + 8 * s, STAGE_BYTES);
            TMA2D(sb,         &tmA, (ks + (int)STAGES) * 64, arow, fullb + 8 * s);
            TMA2D(sb + 16384, &tmB, (ks + (int)STAGES) * 64, brow, fullb + 8 * s);
        }
        if (++s == (int)STAGES) { s = 0; ph ^= 1; }
    }
    #undef LDA4
    #undef LDB2

    #pragma unroll
    for (int mi = 0; mi < 4; mi++) {
        int tok0 = mt * 128 + wm * 64 + mi * 16 + g;
        float* p0 = out + (size_t)(e * NT + tok0) * NH + nt * 128 + wn * 64;
        float* p1 = p0 + (size_t)8 * NH;
        #pragma unroll
        for (int nj = 0; nj < 8; nj++) {
            int colo = nj * 8 + 2 * tig;
            float2 v0 = {acc[mi][nj][0], acc[mi][nj][1]};
            float2 v1 = {acc[mi][nj][2], acc[mi][nj][3]};
            *reinterpret_cast<float2*>(p0 + colo) = v0;
            *reinterpret_cast<float2*>(p1 + colo) = v1;
        }
    }
}

// ============================================================================
// Host
// ============================================================================
typedef CUresult (*EncodeFn)(CUtensorMap*, CUtensorMapDataType, cuuint32_t, void*,
                             const cuuint64_t*, const cuuint64_t*, const cuuint32_t*,
                             const cuuint32_t*, CUtensorMapInterleave, CUtensorMapSwizzle,
                             CUtensorMapL2promotion, CUtensorMapFloatOOBfill);

static void encode2d_h(EncodeFn fn, CUtensorMap* m, void* p,
                       uint64_t d0, uint64_t d1, uint64_t stride_bytes,
                       uint32_t b0, uint32_t b1) {
    cuuint64_t dims[2] = {d0, d1};
    cuuint64_t st[1]   = {stride_bytes};
    cuuint32_t box[2]  = {b0, b1};
    cuuint32_t es[2]   = {1, 1};
    fn(m, CU_TENSOR_MAP_DATA_TYPE_FLOAT16, 2, p, dims, st, box, es,
       CU_TENSOR_MAP_INTERLEAVE_NONE, CU_TENSOR_MAP_SWIZZLE_128B,
       CU_TENSOR_MAP_L2_PROMOTION_L2_128B, CU_TENSOR_MAP_FLOAT_OOB_FILL_NONE);
}

extern "C" void kernel_launch(void* const* d_in, const int* in_sizes, int n_in,
                              void* d_out, int out_size) {
    void* X  = d_in[0];  // (E*T, H) fp32
    void* W1 = d_in[1];  // (E, 2I, H) fp32
    void* W2 = d_in[2];  // (E, H, I) fp32

    void* pfn = nullptr;
    cudaDriverEntryPointQueryResult qr;
#if CUDART_VERSION >= 12050
    cudaGetDriverEntryPointByVersion("cuTensorMapEncodeTiled", &pfn, 12000,
                                     cudaEnableDefault, &qr);
#else
    cudaGetDriverEntryPoint("cuTensorMapEncodeTiled", &pfn, cudaEnableDefault, &qr);
#endif
    EncodeFn enc = (EncodeFn)pfn;

    void *xh, *w1h, *w2h, *acth;
    cudaGetSymbolAddress(&xh,  g_xh);
    cudaGetSymbolAddress(&w1h, g_w1h);
    cudaGetSymbolAddress(&w2h, g_w2h);
    cudaGetSymbolAddress(&acth, g_act_h);

    CUtensorMap tA, tB, tA2, tB2;
    encode2d_h(enc, &tA,  xh,   NH, (uint64_t)NE * NT,     (uint64_t)NH * 2, 64, 128);
    encode2d_h(enc, &tB,  w1h,  NH, (uint64_t)NE * 2 * NI, (uint64_t)NH * 2, 64, 64);
    encode2d_h(enc, &tA2, acth, NI, (uint64_t)NE * NT,     (uint64_t)NI * 2, 64, 128);
    encode2d_h(enc, &tB2, w2h,  NI, (uint64_t)NE * NH,     (uint64_t)NI * 2, 64, 128);

    cudaFuncSetAttribute(moe_gemm1, cudaFuncAttributeMaxDynamicSharedMemorySize, SMEM_ASK);
    cudaFuncSetAttribute(moe_gemm2, cudaFuncAttributeMaxDynamicSharedMemorySize, SMEM_ASK);

    // stream fork: conv chunks on s1, gemm1 chunks on the default stream wait
    // on per-chunk events. Pure graph dependencies (capture-safe fork/join).
    cudaStream_t s1;
    cudaStreamCreateWithFlags(&s1, cudaStreamNonBlocking);
    cudaEvent_t evF, ev[3];
    cudaEventCreateWithFlags(&evF, cudaEventDisableTiming);
    for (int c = 0; c < 3; c++) cudaEventCreateWithFlags(&ev[c], cudaEventDisableTiming);

    static const int CH[4] = {0, 2, 6, 16};

    cudaEventRecord(evF, 0);
    cudaStreamWaitEvent(s1, evF, 0);
    for (int c = 0; c < 3; c++) {
        int ne = CH[c + 1] - CH[c];
        conv_chunk<<<ne * 512, 256, 0, s1>>>((const float4*)X, (const float4*)W1,
                                             CH[c], CH[c + 1]);
        cudaEventRecord(ev[c], s1);
    }
    for (int c = 0; c < 3; c++) {
        cudaStreamWaitEvent(0, ev[c], 0);
        int ne = CH[c + 1] - CH[c];
        moe_gemm1<<<ne * 256, 128, SMEM_ASK>>>(tA, tB, (const float4*)W2, CH[c]);
    }
    moe_gemm2<<<NE * 4 * 16, 128, SMEM_ASK>>>(tA2, tB2, (float*)d_out);
}

// round 13
// speedup vs baseline: 1.5253x; 1.1172x over previous
#include <cuda_runtime.h>
#include <cuda.h>
#include <cuda_fp16.h>
#include <cstdint>

#define NE 16
#define NT 512
#define NH 2048
#define NI 4096

// scratch (allocation-free rule: __device__ globals)
__device__ __align__(1024) __half g_act_h[(size_t)NE * NT * NI];      // 67MB
__device__ __align__(1024) __half g_xh[(size_t)NE * NT * NH];         // 34MB
__device__ __align__(1024) __half g_w2h[(size_t)NE * NH * NI];        // 268MB

// ---------------- device helpers ----------------
__device__ __forceinline__ uint32_t smem_u32(const void* p) {
    uint32_t a;
    asm("{ .reg .u64 t; cvta.to.shared.u64 t, %1; cvt.u32.u64 %0, t; }" : "=r"(a) : "l"(p));
    return a;
}

#define MBAR_INIT(addr, cnt) \
    asm volatile("mbarrier.init.shared.b64 [%0], %1;" :: "r"(addr), "r"(cnt) : "memory")
#define MBAR_EXPECT_TX(addr, bytes) \
    asm volatile("mbarrier.arrive.expect_tx.shared.b64 _, [%0], %1;" :: "r"(addr), "r"(bytes) : "memory")
#define MBAR_ARRIVE(addr) \
    asm volatile("mbarrier.arrive.shared.b64 _, [%0];" :: "r"(addr) : "memory")
#define WAIT_PAR(addr, ph) do {                                                  \
    uint32_t _a = (addr), _p = (ph);                                             \
    asm volatile("{\n\t.reg .pred P;\n\t"                                        \
                 "WL_%=:\n\t"                                                    \
                 "mbarrier.try_wait.parity.shared.b64 P, [%0], %1, 0x989680;\n\t"\
                 "@!P bra WL_%=;\n\t}" :: "r"(_a), "r"(_p) : "memory");          \
} while (0)

#define OPAQUE(x) asm volatile("" : "+r"(x))

#define TMA2D(smem, map, x, y, mbar)                                                          \
    asm volatile("cp.async.bulk.tensor.2d.shared::cta.global.tile.mbarrier::complete_tx::bytes " \
                 "[%0], [%1, {%2, %3}], [%4];"                                                \
                 :: "r"(smem), "l"(map), "r"(x), "r"(y), "r"(mbar) : "memory")

__device__ __forceinline__ uint32_t lds_u32(uint32_t addr) {
    uint32_t v;
    asm("ld.shared.b32 %0, [%1];" : "=r"(v) : "r"(addr));
    return v;
}

// load 2 adjacent fp32 from smem, convert+pack to half2 (pure: schedulable)
__device__ __forceinline__ uint32_t lds2_h2(uint32_t addr) {
    uint32_t r;
    asm("{\n\t.reg .f32 x, y;\n\tld.shared.v2.f32 {x, y}, [%1];\n\t"
        ".reg .b16 a, b;\n\tcvt.rn.f16.f32 a, x;\n\tcvt.rn.f16.f32 b, y;\n\t"
        "mov.b32 %0, {a, b};\n\t}" : "=r"(r) : "r"(addr));
    return r;
}

__device__ __forceinline__ uint32_t pack_h2(float lo, float hi) {
    uint32_t r;
    asm("{\n\t.reg .b16 a, b;\n\tcvt.rn.f16.f32 a, %1;\n\tcvt.rn.f16.f32 b, %2;\n\t"
        "mov.b32 %0, {a, b};\n\t}" : "=r"(r) : "f"(lo), "f"(hi));
    return r;
}

#define MMA_F16(c, a0, a1, a2, a3, b0, b1)                                       \
    asm volatile("mma.sync.aligned.m16n8k16.row.col.f32.f16.f16.f32 "            \
                 "{%0,%1,%2,%3}, {%4,%5,%6,%7}, {%8,%9}, {%0,%1,%2,%3};"         \
                 : "+f"((c)[0]), "+f"((c)[1]), "+f"((c)[2]), "+f"((c)[3])        \
                 : "r"(a0), "r"(a1), "r"(a2), "r"(a3), "r"(b0), "r"(b1))

// gemm2 pipeline (unchanged from R9)
static constexpr uint32_t STAGES2 = 3;
static constexpr uint32_t STAGE2_BYTES = 32768;
static constexpr uint32_t SMEM_ASK2 = STAGES2 * STAGE2_BYTES + 2048;

// gemm1 pipeline: A fp16 16KB + Bg fp32 16KB + Bu fp32 16KB per stage
static constexpr uint32_t STAGES1 = 2;
static constexpr uint32_t STAGE1_BYTES = 49152;
static constexpr uint32_t SMEM_ASK1 = STAGES1 * STAGE1_BYTES + 2048;

// ============================================================================
// X fp32 -> fp16 (tiny prepass, ~0.1GB traffic)
// ============================================================================
__global__ void conv_x(const float4* __restrict__ src, uint2* __restrict__ dst, int n4) {
    int i = blockIdx.x * blockDim.x + threadIdx.x;
    int stride = gridDim.x * blockDim.x;
    #pragma unroll 2
    for (; i < n4; i += stride) {
        float4 v = src[i];
        uint2 o;
        o.x = pack_h2(v.x, v.y);
        o.y = pack_h2(v.z, v.w);
        dst[i] = o;
    }
}

// ============================================================================
// GEMM1: act = up * silu(gate). CTA 128 tok x 64 act-cols, 4 warps,
// warp tile 64 x (32g + 32u), 2 CTAs/SM. A fp16 from g_xh; W1 read DIRECTLY
// as fp32 via TMA, converted fp32->fp16 in the fragment path.
// W2-conv slice in preamble (hidden; gemm2 runs after on the stream).
// ============================================================================
__global__ void __launch_bounds__(128, 2) moe_gemm1(
    const __grid_constant__ CUtensorMap tmA,
    const __grid_constant__ CUtensorMap tmB32,
    const float4* __restrict__ w2src) {
    extern __shared__ __align__(16) char dsm[];
    int tid = threadIdx.x;
    int b = blockIdx.x;
    int mt = b & 3, nt = (b >> 2) & 63, e = b >> 8;
    int arow = e * NT + mt * 128;
    int grow = e * (2 * NI) + nt * 64;
    int urow = grow + NI;

    uint32_t base = (smem_u32(dsm) + 1023u) & ~1023u;
    uint32_t fullb = base + STAGES1 * STAGE1_BYTES;
    uint32_t emptb = fullb + 64;

    int wid = tid >> 5, lane = tid & 31;
    int g = lane >> 2, tig = lane & 3;
    int wm = wid >> 1, wn = wid & 1;
    uint32_t xr = (uint32_t)g << 4;

    if (tid == 0) {
        for (uint32_t s = 0; s < STAGES1; s++) { MBAR_INIT(fullb + 8 * s, 1); MBAR_INIT(emptb + 8 * s, 4); }
        asm volatile("fence.proxy.async.shared::cta;" ::: "memory");
    }
    __syncthreads();

    // stage layout: A @0 (16KB fp16, k=64), Bg @16384 (2x 8KB fp32 tiles, k=32+32),
    //               Bu @32768 (same). 6 TMA per stage.
    if (tid == 0) {
        for (uint32_t c = 0; c < STAGES1; c++) {
            uint32_t sb = base + c * STAGE1_BYTES;
            MBAR_EXPECT_TX(fullb + 8 * c, STAGE1_BYTES);
            TMA2D(sb,                 &tmA,   (int)c * 64,      arow, fullb + 8 * c);
            TMA2D(sb + 16384,         &tmB32, (int)c * 64,      grow, fullb + 8 * c);
            TMA2D(sb + 16384 + 8192,  &tmB32, (int)c * 64 + 32, grow, fullb + 8 * c);
            TMA2D(sb + 32768,         &tmB32, (int)c * 64,      urow, fullb + 8 * c);
            TMA2D(sb + 32768 + 8192,  &tmB32, (int)c * 64 + 32, urow, fullb + 8 * c);
        }
    }

    // W2 conversion slice (overlaps pipeline fill + early mainloop)
    {
        int o = e * 256 + (b & 255);     // 0..4095
        const float4* src = w2src + (size_t)o * 8192;
        uint2* dst = reinterpret_cast<uint2*>(g_w2h) + (size_t)o * 8192;
        #pragma unroll 4
        for (int i = tid; i < 8192; i += 128) {
            float4 v = src[i];
            uint2 o2;
            o2.x = pack_h2(v.x, v.y);
            o2.y = pack_h2(v.z, v.w);
            dst[i] = o2;
        }
    }

    float accg[4][4][4], accu[4][4][4];
    #pragma unroll
    for (int i = 0; i < 4; i++)
        #pragma unroll
        for (int j = 0; j < 4; j++)
            #pragma unroll
            for (int q = 0; q < 4; q++) { accg[i][j][q] = 0.f; accu[i][j][q] = 0.f; }

    uint32_t rowA[4];
    #pragma unroll
    for (int mi = 0; mi < 4; mi++) rowA[mi] = (uint32_t)(wm * 64 + mi * 16 + g) * 128;
    uint32_t rowB = (uint32_t)(wn * 32 + g) * 128;   // fp32 tiles also have 128B rows

    // A (fp16) column byte offsets per k16 chunk
    uint32_t C0[4], C1[4];
    #pragma unroll
    for (int kk = 0; kk < 4; kk++) {
        C0[kk] = ((uint32_t)(kk * 32 + tig * 4)) ^ xr;
        C1[kk] = ((uint32_t)(kk * 32 + 16 + tig * 4)) ^ xr;
    }
    // B (fp32) column byte offsets per k16 chunk: floats {2tig,2tig+1} and +8
    uint32_t D0[4], D1[4], TOFF[4];
    #pragma unroll
    for (int kk = 0; kk < 4; kk++) {
        D0[kk] = ((uint32_t)((kk & 1) * 64 + tig * 8)) ^ xr;
        D1[kk] = ((uint32_t)((kk & 1) * 64 + tig * 8 + 32)) ^ xr;
        TOFF[kk] = (uint32_t)(kk >> 1) * 8192;
    }

    uint32_t Af[2][16], Bg[2][2], Bu[2][2];

    #define LDA4g(buf, sA, kk, mi) do {                                          \
        Af[buf][(mi) * 4 + 0] = lds_u32((sA) + rowA[mi] + C0[kk]);               \
        Af[buf][(mi) * 4 + 1] = lds_u32((sA) + rowA[mi] + 1024 + C0[kk]);        \
        Af[buf][(mi) * 4 + 2] = lds_u32((sA) + rowA[mi] + C1[kk]);               \
        Af[buf][(mi) * 4 + 3] = lds_u32((sA) + rowA[mi] + 1024 + C1[kk]);        \
    } while (0)
    #define LDGU(buf, sA, kk, nj) do {                                           \
        uint32_t _r = TOFF[kk] + rowB + (uint32_t)(nj) * 1024;                   \
        Bg[buf][0] = lds2_h2((sA) + 16384 + _r + D0[kk]);                        \
        Bg[buf][1] = lds2_h2((sA) + 16384 + _r + D1[kk]);                        \
        Bu[buf][0] = lds2_h2((sA) + 32768 + _r + D0[kk]);                        \
        Bu[buf][1] = lds2_h2((sA) + 32768 + _r + D1[kk]);                        \
    } while (0)

    int s = 0, ph = 0;
    #pragma unroll 1
    for (int ks = 0; ks < 32; ks++) {
        WAIT_PAR(fullb + 8 * s, ph);
        uint32_t sA = base + (uint32_t)s * STAGE1_BYTES;
        OPAQUE(sA);

        #pragma unroll
        for (int mi = 0; mi < 4; mi++) LDA4g(0, sA, 0, mi);
        LDGU(0, sA, 0, 0);

        #pragma unroll
        for (int kk = 0; kk < 4; kk++) {
            #pragma unroll
            for (int nj = 0; nj < 4; nj++) {
                int grp = kk * 4 + nj;
                int cb = grp & 1;
                if (nj < 3)       LDGU(cb ^ 1, sA, kk, nj + 1);
                else if (kk < 3)  LDGU(cb ^ 1, sA, kk + 1, 0);
                if (kk < 3) LDA4g((kk + 1) & 1, sA, kk + 1, nj);
                int ab = kk & 1;
                #pragma unroll
                for (int mi = 0; mi < 4; mi++) {
                    MMA_F16(accg[mi][nj], Af[ab][mi * 4 + 0], Af[ab][mi * 4 + 1],
                            Af[ab][mi * 4 + 2], Af[ab][mi * 4 + 3],
                            Bg[cb][0], Bg[cb][1]);
                    MMA_F16(accu[mi][nj], Af[ab][mi * 4 + 0], Af[ab][mi * 4 + 1],
                            Af[ab][mi * 4 + 2], Af[ab][mi * 4 + 3],
                            Bu[cb][0], Bu[cb][1]);
                }
            }
        }
        if (lane == 0) MBAR_ARRIVE(emptb + 8 * s);
        if (tid == 0 && ks + (int)STAGES1 < 32) {
            WAIT_PAR(emptb + 8 * s, ph);
            uint32_t sb = base + (uint32_t)s * STAGE1_BYTES;
            int kn = (ks + (int)STAGES1) * 64;
            MBAR_EXPECT_TX(fullb + 8 * s, STAGE1_BYTES);
            TMA2D(sb,                &tmA,   kn,      arow, fullb + 8 * s);
            TMA2D(sb + 16384,        &tmB32, kn,      grow, fullb + 8 * s);
            TMA2D(sb + 16384 + 8192, &tmB32, kn + 32, grow, fullb + 8 * s);
            TMA2D(sb + 32768,        &tmB32, kn,      urow, fullb + 8 * s);
            TMA2D(sb + 32768 + 8192, &tmB32, kn + 32, urow, fullb + 8 * s);
        }
        if (++s == (int)STAGES1) { s = 0; ph ^= 1; }
    }
    #undef LDA4g
    #undef LDGU

    // Epilogue: SwiGLU -> fp16 act
    #pragma unroll
    for (int mi = 0; mi < 4; mi++) {
        int tok0 = mt * 128 + wm * 64 + mi * 16 + g;
        __half* p0 = g_act_h + (size_t)(e * NT + tok0) * NI + nt * 64 + wn * 32;
        __half* p1 = p0 + (size_t)8 * NI;
        #pragma unroll
        for (int nj = 0; nj < 4; nj++) {
            int colo = nj * 8 + 2 * tig;
            float v00, v01, v10, v11;
            float gg = accg[mi][nj][0], uu = accu[mi][nj][0];
            v00 = uu * gg / (1.0f + __expf(-gg));
            gg = accg[mi][nj][1]; uu = accu[mi][nj][1];
            v01 = uu * gg / (1.0f + __expf(-gg));
            gg = accg[mi][nj][2]; uu = accu[mi][nj][2];
            v10 = uu * gg / (1.0f + __expf(-gg));
            gg = accg[mi][nj][3]; uu = accu[mi][nj][3];
            v11 = uu * gg / (1.0f + __expf(-gg));
            *reinterpret_cast<uint32_t*>(p0 + colo) = pack_h2(v00, v01);
            *reinterpret_cast<uint32_t*>(p1 + colo) = pack_h2(v10, v11);
        }
    }
}

// ============================================================================
// GEMM2: out = act @ W2^T. CTA 128x128, 4 warps, warp tile 64x64, 2 CTAs/SM.
// (unchanged from R9)
// ============================================================================
__global__ void __launch_bounds__(128, 2) moe_gemm2(
    const __grid_constant__ CUtensorMap tmA,
    const __grid_constant__ CUtensorMap tmB,
    float* __restrict__ out) {
    extern __shared__ __align__(16) char dsm[];
    uint32_t base = (smem_u32(dsm) + 1023u) & ~1023u;
    uint32_t fullb = base + STAGES2 * STAGE2_BYTES;
    uint32_t emptb = fullb + 64;

    int tid = threadIdx.x, wid = tid >> 5, lane = tid & 31;
    int g = lane >> 2, tig = lane & 3;
    int wm = wid >> 1, wn = wid & 1;
    uint32_t xr = (uint32_t)g << 4;

    int b = blockIdx.x;
    int mt = b & 3, nt = (b >> 2) & 15, e = b >> 6;
    int arow = e * NT + mt * 128;
    int brow = e * NH + nt * 128;

    if (tid == 0) {
        for (uint32_t s = 0; s < STAGES2; s++) { MBAR_INIT(fullb + 8 * s, 1); MBAR_INIT(emptb + 8 * s, 4); }
        asm volatile("fence.proxy.async.shared::cta;" ::: "memory");
    }
    __syncthreads();

    if (tid == 0) {
        for (uint32_t c = 0; c < STAGES2; c++) {
            uint32_t sb = base + c * STAGE2_BYTES;
            MBAR_EXPECT_TX(fullb + 8 * c, STAGE2_BYTES);
            TMA2D(sb,         &tmA, (int)c * 64, arow, fullb + 8 * c);
            TMA2D(sb + 16384, &tmB, (int)c * 64, brow, fullb + 8 * c);
        }
    }

    float acc[4][8][4];
    #pragma unroll
    for (int i = 0; i < 4; i++)
        #pragma unroll
        for (int j = 0; j < 8; j++)
            #pragma unroll
            for (int q = 0; q < 4; q++) acc[i][j][q] = 0.f;

    uint32_t rowA[4];
    #pragma unroll
    for (int mi = 0; mi < 4; mi++) rowA[mi] = (uint32_t)(wm * 64 + mi * 16 + g) * 128;
    uint32_t rowB = (uint32_t)(wn * 64 + g) * 128;

    uint32_t C0[4], C1[4];
    #pragma unroll
    for (int kk = 0; kk < 4; kk++) {
        C0[kk] = ((uint32_t)(kk * 32 + tig * 4)) ^ xr;
        C1[kk] = ((uint32_t)(kk * 32 + 16 + tig * 4)) ^ xr;
    }

    uint32_t Af[2][16], Bf[2][2];

    #define LDA4(buf, sA, kk, mi) do {                                           \
        Af[buf][(mi) * 4 + 0] = lds_u32((sA) + rowA[mi] + C0[kk]);               \
        Af[buf][(mi) * 4 + 1] = lds_u32((sA) + rowA[mi] + 1024 + C0[kk]);        \
        Af[buf][(mi) * 4 + 2] = lds_u32((sA) + rowA[mi] + C1[kk]);               \
        Af[buf][(mi) * 4 + 3] = lds_u32((sA) + rowA[mi] + 1024 + C1[kk]);        \
    } while (0)
    #define LDB2(buf, sB, kk, nj) do {                                           \
        Bf[buf][0] = lds_u32((sB) + rowB + (uint32_t)(nj) * 1024 + C0[kk]);      \
        Bf[buf][1] = lds_u32((sB) + rowB + (uint32_t)(nj) * 1024 + C1[kk]);      \
    } while (0)

    int s = 0, ph = 0;
    #pragma unroll 1
    for (int ks = 0; ks < 64; ks++) {
        WAIT_PAR(fullb + 8 * s, ph);
        uint32_t sA = base + (uint32_t)s * STAGE2_BYTES;
        OPAQUE(sA);
        uint32_t sB = sA + 16384;

        #pragma unroll
        for (int mi = 0; mi < 4; mi++) LDA4(0, sA, 0, mi);
        LDB2(0, sB, 0, 0);

        #pragma unroll
        for (int kk = 0; kk < 4; kk++) {
            #pragma unroll
            for (int nj = 0; nj < 8; nj++) {
                int grp = kk * 8 + nj;
                int cb = grp & 1;
                if (nj < 7)       LDB2(cb ^ 1, sB, kk, nj + 1);
                else if (kk < 3)  LDB2(cb ^ 1, sB, kk + 1, 0);
                if (kk < 3 && nj >= 4) LDA4((kk + 1) & 1, sA, kk + 1, nj - 4);
                int ab = kk & 1;
                #pragma unroll
                for (int mi = 0; mi < 4; mi++)
                    MMA_F16(acc[mi][nj], Af[ab][mi * 4 + 0], Af[ab][mi * 4 + 1],
                            Af[ab][mi * 4 + 2], Af[ab][mi * 4 + 3],
                            Bf[cb][0], Bf[cb][1]);
            }
        }
        if (lane == 0) MBAR_ARRIVE(emptb + 8 * s);
        if (tid == 0 && ks + (int)STAGES2 < 64) {
            WAIT_PAR(emptb + 8 * s, ph);
            uint32_t sb = base + (uint32_t)s * STAGE2_BYTES;
            MBAR_EXPECT_TX(fullb + 8 * s, STAGE2_BYTES);
            TMA2D(sb,         &tmA, (ks + (int)STAGES2) * 64, arow, fullb + 8 * s);
            TMA2D(sb + 16384, &tmB, (ks + (int)STAGES2) * 64, brow, fullb + 8 * s);
        }
        if (++s == (int)STAGES2) { s = 0; ph ^= 1; }
    }
    #undef LDA4
    #undef LDB2

    #pragma unroll
    for (int mi = 0; mi < 4; mi++) {
        int tok0 = mt * 128 + wm * 64 + mi * 16 + g;
        float* p0 = out + (size_t)(e * NT + tok0) * NH + nt * 128 + wn * 64;
        float* p1 = p0 + (size_t)8 * NH;
        #pragma unroll
        for (int nj = 0; nj < 8; nj++) {
            int colo = nj * 8 + 2 * tig;
            float2 v0 = {acc[mi][nj][0], acc[mi][nj][1]};
            float2 v1 = {acc[mi][nj][2], acc[mi][nj][3]};
            *reinterpret_cast<float2*>(p0 + colo) = v0;
            *reinterpret_cast<float2*>(p1 + colo) = v1;
        }
    }
}

// ============================================================================
// Host
// ============================================================================
typedef CUresult (*EncodeFn)(CUtensorMap*, CUtensorMapDataType, cuuint32_t, void*,
                             const cuuint64_t*, const cuuint64_t*, const cuuint32_t*,
                             const cuuint32_t*, CUtensorMapInterleave, CUtensorMapSwizzle,
                             CUtensorMapL2promotion, CUtensorMapFloatOOBfill);

static void encode2d(EncodeFn fn, CUtensorMap* m, void* p, CUtensorMapDataType dt,
                     uint64_t d0, uint64_t d1, uint64_t stride_bytes,
                     uint32_t b0, uint32_t b1) {
    cuuint64_t dims[2] = {d0, d1};
    cuuint64_t st[1]   = {stride_bytes};
    cuuint32_t box[2]  = {b0, b1};
    cuuint32_t es[2]   = {1, 1};
    fn(m, dt, 2, p, dims, st, box, es,
       CU_TENSOR_MAP_INTERLEAVE_NONE, CU_TENSOR_MAP_SWIZZLE_128B,
       CU_TENSOR_MAP_L2_PROMOTION_L2_128B, CU_TENSOR_MAP_FLOAT_OOB_FILL_NONE);
}

extern "C" void kernel_launch(void* const* d_in, const int* in_sizes, int n_in,
                              void* d_out, int out_size) {
    void* X  = d_in[0];  // (E*T, H) fp32
    void* W1 = d_in[1];  // (E, 2I, H) fp32
    void* W2 = d_in[2];  // (E, H, I) fp32

    void* pfn = nullptr;
    cudaDriverEntryPointQueryResult qr;
#if CUDART_VERSION >= 12050
    cudaGetDriverEntryPointByVersion("cuTensorMapEncodeTiled", &pfn, 12000,
                                     cudaEnableDefault, &qr);
#else
    cudaGetDriverEntryPoint("cuTensorMapEncodeTiled", &pfn, cudaEnableDefault, &qr);
#endif
    EncodeFn enc = (EncodeFn)pfn;

    void *xh, *w2h, *acth;
    cudaGetSymbolAddress(&xh,  g_xh);
    cudaGetSymbolAddress(&w2h, g_w2h);
    cudaGetSymbolAddress(&acth, g_act_h);

    CUtensorMap tA, tB32, tA2, tB2;
    encode2d(enc, &tA,   xh,  CU_TENSOR_MAP_DATA_TYPE_FLOAT16,
             NH, (uint64_t)NE * NT,     (uint64_t)NH * 2, 64, 128);
    encode2d(enc, &tB32, W1,  CU_TENSOR_MAP_DATA_TYPE_FLOAT32,
             NH, (uint64_t)NE * 2 * NI, (uint64_t)NH * 4, 32, 64);
    encode2d(enc, &tA2,  acth, CU_TENSOR_MAP_DATA_TYPE_FLOAT16,
             NI, (uint64_t)NE * NT,     (uint64_t)NI * 2, 64, 128);
    encode2d(enc, &tB2,  w2h, CU_TENSOR_MAP_DATA_TYPE_FLOAT16,
             NI, (uint64_t)NE * NH,     (uint64_t)NI * 2, 64, 128);

    cudaFuncSetAttribute(moe_gemm1, cudaFuncAttributeMaxDynamicSharedMemorySize, SMEM_ASK1);
    cudaFuncSetAttribute(moe_gemm2, cudaFuncAttributeMaxDynamicSharedMemorySize, SMEM_ASK2);

    // tiny prepass: X -> fp16 (~0.1GB traffic)
    int n4x = NE * NT * NH / 4;
    conv_x<<<4096, 256>>>((const float4*)X, (uint2*)xh, n4x);

    moe_gemm1<<<NE * 256, 128, SMEM_ASK1>>>(tA, tB32, (const float4*)W2);
    moe_gemm2<<<NE * 64, 128, SMEM_ASK2>>>(tA2, tB2, (float*)d_out);
}

// round 14
// speedup vs baseline: 1.5266x; 1.0008x over previous
#include <cuda_runtime.h>
#include <cuda.h>
#include <cuda_fp16.h>
#include <cstdint>

#define NE 16
#define NT 512
#define NH 2048
#define NI 4096

// scratch (allocation-free rule: __device__ globals)
__device__ __align__(1024) __half g_act_h[(size_t)NE * NT * NI];      // 67MB
__device__ __align__(1024) __half g_xh[(size_t)NE * NT * NH];         // 34MB
__device__ __align__(1024) __half g_w2h[(size_t)NE * NH * NI];        // 268MB

// ---------------- device helpers ----------------
__device__ __forceinline__ uint32_t smem_u32(const void* p) {
    uint32_t a;
    asm("{ .reg .u64 t; cvta.to.shared.u64 t, %1; cvt.u32.u64 %0, t; }" : "=r"(a) : "l"(p));
    return a;
}

#define MBAR_INIT(addr, cnt) \
    asm volatile("mbarrier.init.shared.b64 [%0], %1;" :: "r"(addr), "r"(cnt) : "memory")
#define MBAR_EXPECT_TX(addr, bytes) \
    asm volatile("mbarrier.arrive.expect_tx.shared.b64 _, [%0], %1;" :: "r"(addr), "r"(bytes) : "memory")
#define MBAR_ARRIVE(addr) \
    asm volatile("mbarrier.arrive.shared.b64 _, [%0];" :: "r"(addr) : "memory")
#define WAIT_PAR(addr, ph) do {                                                  \
    uint32_t _a = (addr), _p = (ph);                                             \
    asm volatile("{\n\t.reg .pred P;\n\t"                                        \
                 "WL_%=:\n\t"                                                    \
                 "mbarrier.try_wait.parity.shared.b64 P, [%0], %1, 0x989680;\n\t"\
                 "@!P bra WL_%=;\n\t}" :: "r"(_a), "r"(_p) : "memory");          \
} while (0)

#define OPAQUE(x) asm volatile("" : "+r"(x))

#define TMA2D(smem, map, x, y, mbar)                                                          \
    asm volatile("cp.async.bulk.tensor.2d.shared::cta.global.tile.mbarrier::complete_tx::bytes " \
                 "[%0], [%1, {%2, %3}], [%4];"                                                \
                 :: "r"(smem), "l"(map), "r"(x), "r"(y), "r"(mbar) : "memory")

__device__ __forceinline__ uint32_t lds_u32(uint32_t addr) {
    uint32_t v;
    asm("ld.shared.b32 %0, [%1];" : "=r"(v) : "r"(addr));
    return v;
}

// load 2 adjacent fp32 from smem, convert+pack to half2 (pure: schedulable)
__device__ __forceinline__ uint32_t lds2_h2(uint32_t addr) {
    uint32_t r;
    asm("{\n\t.reg .f32 x, y;\n\tld.shared.v2.f32 {x, y}, [%1];\n\t"
        ".reg .b16 a, b;\n\tcvt.rn.f16.f32 a, x;\n\tcvt.rn.f16.f32 b, y;\n\t"
        "mov.b32 %0, {a, b};\n\t}" : "=r"(r) : "r"(addr));
    return r;
}

__device__ __forceinline__ uint32_t pack_h2(float lo, float hi) {
    uint32_t r;
    asm("{\n\t.reg .b16 a, b;\n\tcvt.rn.f16.f32 a, %1;\n\tcvt.rn.f16.f32 b, %2;\n\t"
        "mov.b32 %0, {a, b};\n\t}" : "=r"(r) : "f"(lo), "f"(hi));
    return r;
}

#define MMA_F16(c, a0, a1, a2, a3, b0, b1)                                       \
    asm volatile("mma.sync.aligned.m16n8k16.row.col.f32.f16.f16.f32 "            \
                 "{%0,%1,%2,%3}, {%4,%5,%6,%7}, {%8,%9}, {%0,%1,%2,%3};"         \
                 : "+f"((c)[0]), "+f"((c)[1]), "+f"((c)[2]), "+f"((c)[3])        \
                 : "r"(a0), "r"(a1), "r"(a2), "r"(a3), "r"(b0), "r"(b1))

// gemm2 pipeline (unchanged from R9)
static constexpr uint32_t STAGES2 = 3;
static constexpr uint32_t STAGE2_BYTES = 32768;
static constexpr uint32_t SMEM_ASK2 = STAGES2 * STAGE2_BYTES + 2048;

// gemm1 pipeline: A fp16 16KB + Bg fp32 16KB + Bu fp32 16KB per stage
static constexpr uint32_t STAGES1 = 2;
static constexpr uint32_t STAGE1_BYTES = 49152;
static constexpr uint32_t SMEM_ASK1 = STAGES1 * STAGE1_BYTES + 2048;

// ============================================================================
// X fp32 -> fp16 (tiny prepass, ~0.1GB traffic)
// ============================================================================
__global__ void conv_x(const float4* __restrict__ src, uint2* __restrict__ dst, int n4) {
    int i = blockIdx.x * blockDim.x + threadIdx.x;
    int stride = gridDim.x * blockDim.x;
    #pragma unroll 2
    for (; i < n4; i += stride) {
        float4 v = src[i];
        uint2 o;
        o.x = pack_h2(v.x, v.y);
        o.y = pack_h2(v.z, v.w);
        dst[i] = o;
    }
}

// ============================================================================
// GEMM1: act = up * silu(gate). CTA 128 tok x 64 act-cols, 4 warps,
// warp tile 64 x (32g + 32u), 2 CTAs/SM. A fp16 from g_xh; W1 read DIRECTLY
// as fp32 via TMA, converted fp32->fp16 in the fragment path.
// W2-conv slice in preamble (hidden; gemm2 runs after on the stream).
// ============================================================================
__global__ void __launch_bounds__(128, 2) moe_gemm1(
    const __grid_constant__ CUtensorMap tmA,
    const __grid_constant__ CUtensorMap tmB32,
    const float4* __restrict__ w2src) {
    extern __shared__ __align__(16) char dsm[];
    int tid = threadIdx.x;
    int b = blockIdx.x;
    int mt = b & 3, nt = (b >> 2) & 63, e = b >> 8;
    int arow = e * NT + mt * 128;
    int grow = e * (2 * NI) + nt * 64;
    int urow = grow + NI;

    uint32_t base = (smem_u32(dsm) + 1023u) & ~1023u;
    uint32_t fullb = base + STAGES1 * STAGE1_BYTES;
    uint32_t emptb = fullb + 64;

    int wid = tid >> 5, lane = tid & 31;
    int g = lane >> 2, tig = lane & 3;
    int wm = wid >> 1, wn = wid & 1;
    uint32_t xr = (uint32_t)g << 4;

    if (tid == 0) {
        for (uint32_t s = 0; s < STAGES1; s++) { MBAR_INIT(fullb + 8 * s, 1); MBAR_INIT(emptb + 8 * s, 4); }
        asm volatile("fence.proxy.async.shared::cta;" ::: "memory");
    }
    __syncthreads();

    // stage layout: A @0 (16KB fp16, k=64), Bg @16384 (2x 8KB fp32 tiles, k=32+32),
    //               Bu @32768 (same). 6 TMA per stage.
    if (tid == 0) {
        for (uint32_t c = 0; c < STAGES1; c++) {
            uint32_t sb = base + c * STAGE1_BYTES;
            MBAR_EXPECT_TX(fullb + 8 * c, STAGE1_BYTES);
            TMA2D(sb,                 &tmA,   (int)c * 64,      arow, fullb + 8 * c);
            TMA2D(sb + 16384,         &tmB32, (int)c * 64,      grow, fullb + 8 * c);
            TMA2D(sb + 16384 + 8192,  &tmB32, (int)c * 64 + 32, grow, fullb + 8 * c);
            TMA2D(sb + 32768,         &tmB32, (int)c * 64,      urow, fullb + 8 * c);
            TMA2D(sb + 32768 + 8192,  &tmB32, (int)c * 64 + 32, urow, fullb + 8 * c);
        }
    }

    // W2 conversion slice (overlaps pipeline fill + early mainloop)
    {
        int o = e * 256 + (b & 255);     // 0..4095
        const float4* src = w2src + (size_t)o * 8192;
        uint2* dst = reinterpret_cast<uint2*>(g_w2h) + (size_t)o * 8192;
        #pragma unroll 4
        for (int i = tid; i < 8192; i += 128) {
            float4 v = src[i];
            uint2 o2;
            o2.x = pack_h2(v.x, v.y);
            o2.y = pack_h2(v.z, v.w);
            dst[i] = o2;
        }
    }

    float accg[4][4][4], accu[4][4][4];
    #pragma unroll
    for (int i = 0; i < 4; i++)
        #pragma unroll
        for (int j = 0; j < 4; j++)
            #pragma unroll
            for (int q = 0; q < 4; q++) { accg[i][j][q] = 0.f; accu[i][j][q] = 0.f; }

    uint32_t rowA[4];
    #pragma unroll
    for (int mi = 0; mi < 4; mi++) rowA[mi] = (uint32_t)(wm * 64 + mi * 16 + g) * 128;
    uint32_t rowB = (uint32_t)(wn * 32 + g) * 128;   // fp32 tiles also have 128B rows

    // A (fp16) column byte offsets per k16 chunk
    uint32_t C0[4], C1[4];
    #pragma unroll
    for (int kk = 0; kk < 4; kk++) {
        C0[kk] = ((uint32_t)(kk * 32 + tig * 4)) ^ xr;
        C1[kk] = ((uint32_t)(kk * 32 + 16 + tig * 4)) ^ xr;
    }
    // B (fp32) column byte offsets per k16 chunk: floats {2tig,2tig+1} and +8
    uint32_t D0[4], D1[4], TOFF[4];
    #pragma unroll
    for (int kk = 0; kk < 4; kk++) {
        D0[kk] = ((uint32_t)((kk & 1) * 64 + tig * 8)) ^ xr;
        D1[kk] = ((uint32_t)((kk & 1) * 64 + tig * 8 + 32)) ^ xr;
        TOFF[kk] = (uint32_t)(kk >> 1) * 8192;
    }

    uint32_t Af[2][16], Bg[2][2], Bu[2][2];

    #define LDA4g(buf, sA, kk, mi) do {                                          \
        Af[buf][(mi) * 4 + 0] = lds_u32((sA) + rowA[mi] + C0[kk]);               \
        Af[buf][(mi) * 4 + 1] = lds_u32((sA) + rowA[mi] + 1024 + C0[kk]);        \
        Af[buf][(mi) * 4 + 2] = lds_u32((sA) + rowA[mi] + C1[kk]);               \
        Af[buf][(mi) * 4 + 3] = lds_u32((sA) + rowA[mi] + 1024 + C1[kk]);        \
    } while (0)
    #define LDGU(buf, sA, kk, nj) do {                                           \
        uint32_t _r = TOFF[kk] + rowB + (uint32_t)(nj) * 1024;                   \
        Bg[buf][0] = lds2_h2((sA) + 16384 + _r + D0[kk]);                        \
        Bg[buf][1] = lds2_h2((sA) + 16384 + _r + D1[kk]);                        \
        Bu[buf][0] = lds2_h2((sA) + 32768 + _r + D0[kk]);                        \
        Bu[buf][1] = lds2_h2((sA) + 32768 + _r + D1[kk]);                        \
    } while (0)

    int s = 0, ph = 0;
    #pragma unroll 1
    for (int ks = 0; ks < 32; ks++) {
        WAIT_PAR(fullb + 8 * s, ph);
        uint32_t sA = base + (uint32_t)s * STAGE1_BYTES;
        OPAQUE(sA);

        #pragma unroll
        for (int mi = 0; mi < 4; mi++) LDA4g(0, sA, 0, mi);
        LDGU(0, sA, 0, 0);

        #pragma unroll
        for (int kk = 0; kk < 4; kk++) {
            #pragma unroll
            for (int nj = 0; nj < 4; nj++) {
                int grp = kk * 4 + nj;
                int cb = grp & 1;
                if (nj < 3)       LDGU(cb ^ 1, sA, kk, nj + 1);
                else if (kk < 3)  LDGU(cb ^ 1, sA, kk + 1, 0);
                if (kk < 3) LDA4g((kk + 1) & 1, sA, kk + 1, nj);
                int ab = kk & 1;
                #pragma unroll
                for (int mi = 0; mi < 4; mi++) {
                    MMA_F16(accg[mi][nj], Af[ab][mi * 4 + 0], Af[ab][mi * 4 + 1],
                            Af[ab][mi * 4 + 2], Af[ab][mi * 4 + 3],
                            Bg[cb][0], Bg[cb][1]);
                    MMA_F16(accu[mi][nj], Af[ab][mi * 4 + 0], Af[ab][mi * 4 + 1],
                            Af[ab][mi * 4 + 2], Af[ab][mi * 4 + 3],
                            Bu[cb][0], Bu[cb][1]);
                }
            }
        }
        if (lane == 0) MBAR_ARRIVE(emptb + 8 * s);
        if (tid == 0 && ks + (int)STAGES1 < 32) {
            WAIT_PAR(emptb + 8 * s, ph);
            uint32_t sb = base + (uint32_t)s * STAGE1_BYTES;
            int kn = (ks + (int)STAGES1) * 64;
            MBAR_EXPECT_TX(fullb + 8 * s, STAGE1_BYTES);
            TMA2D(sb,                &tmA,   kn,      arow, fullb + 8 * s);
            TMA2D(sb + 16384,        &tmB32, kn,      grow, fullb + 8 * s);
            TMA2D(sb + 16384 + 8192, &tmB32, kn + 32, grow, fullb + 8 * s);
            TMA2D(sb + 32768,        &tmB32, kn,      urow, fullb + 8 * s);
            TMA2D(sb + 32768 + 8192, &tmB32, kn + 32, urow, fullb + 8 * s);
        }
        if (++s == (int)STAGES1) { s = 0; ph ^= 1; }
    }
    #undef LDA4g
    #undef LDGU

    // Epilogue: SwiGLU -> fp16 act
    #pragma unroll
    for (int mi = 0; mi < 4; mi++) {
        int tok0 = mt * 128 + wm * 64 + mi * 16 + g;
        __half* p0 = g_act_h + (size_t)(e * NT + tok0) * NI + nt * 64 + wn * 32;
        __half* p1 = p0 + (size_t)8 * NI;
        #pragma unroll
        for (int nj = 0; nj < 4; nj++) {
            int colo = nj * 8 + 2 * tig;
            float v00, v01, v10, v11;
            float gg = accg[mi][nj][0], uu = accu[mi][nj][0];
            v00 = uu * gg / (1.0f + __expf(-gg));
            gg = accg[mi][nj][1]; uu = accu[mi][nj][1];
            v01 = uu * gg / (1.0f + __expf(-gg));
            gg = accg[mi][nj][2]; uu = accu[mi][nj][2];
            v10 = uu * gg / (1.0f + __expf(-gg));
            gg = accg[mi][nj][3]; uu = accu[mi][nj][3];
            v11 = uu * gg / (1.0f + __expf(-gg));
            *reinterpret_cast<uint32_t*>(p0 + colo) = pack_h2(v00, v01);
            *reinterpret_cast<uint32_t*>(p1 + colo) = pack_h2(v10, v11);
        }
    }
}

// ============================================================================
// GEMM2: out = act @ W2^T. CTA 128x128, 4 warps, warp tile 64x64, 2 CTAs/SM.
// (unchanged from R9)
// ============================================================================
__global__ void __launch_bounds__(128, 2) moe_gemm2(
    const __grid_constant__ CUtensorMap tmA,
    const __grid_constant__ CUtensorMap tmB,
    float* __restrict__ out) {
    extern __shared__ __align__(16) char dsm[];
    uint32_t base = (smem_u32(dsm) + 1023u) & ~1023u;
    uint32_t fullb = base + STAGES2 * STAGE2_BYTES;
    uint32_t emptb = fullb + 64;

    int tid = threadIdx.x, wid = tid >> 5, lane = tid & 31;
    int g = lane >> 2, tig = lane & 3;
    int wm = wid >> 1, wn = wid & 1;
    uint32_t xr = (uint32_t)g << 4;

    int b = blockIdx.x;
    int mt = b & 3, nt = (b >> 2) & 15, e = b >> 6;
    int arow = e * NT + mt * 128;
    int brow = e * NH + nt * 128;

    if (tid == 0) {
        for (uint32_t s = 0; s < STAGES2; s++) { MBAR_INIT(fullb + 8 * s, 1); MBAR_INIT(emptb + 8 * s, 4); }
        asm volatile("fence.proxy.async.shared::cta;" ::: "memory");
    }
    __syncthreads();

    if (tid == 0) {
        for (uint32_t c = 0; c < STAGES2; c++) {
            uint32_t sb = base + c * STAGE2_BYTES;
            MBAR_EXPECT_TX(fullb + 8 * c, STAGE2_BYTES);
            TMA2D(sb,         &tmA, (int)c * 64, arow, fullb + 8 * c);
            TMA2D(sb + 16384, &tmB, (int)c * 64, brow, fullb + 8 * c);
        }
    }

    float acc[4][8][4];
    #pragma unroll
    for (int i = 0; i < 4; i++)
        #pragma unroll
        for (int j = 0; j < 8; j++)
            #pragma unroll
            for (int q = 0; q < 4; q++) acc[i][j][q] = 0.f;

    uint32_t rowA[4];
    #pragma unroll
    for (int mi = 0; mi < 4; mi++) rowA[mi] = (uint32_t)(wm * 64 + mi * 16 + g) * 128;
    uint32_t rowB = (uint32_t)(wn * 64 + g) * 128;

    uint32_t C0[4], C1[4];
    #pragma unroll
    for (int kk = 0; kk < 4; kk++) {
        C0[kk] = ((uint32_t)(kk * 32 + tig * 4)) ^ xr;
        C1[kk] = ((uint32_t)(kk * 32 + 16 + tig * 4)) ^ xr;
    }

    uint32_t Af[2][16], Bf[2][2];

    #define LDA4(buf, sA, kk, mi) do {                                           \
        Af[buf][(mi) * 4 + 0] = lds_u32((sA) + rowA[mi] + C0[kk]);               \
        Af[buf][(mi) * 4 + 1] = lds_u32((sA) + rowA[mi] + 1024 + C0[kk]);        \
        Af[buf][(mi) * 4 + 2] = lds_u32((sA) + rowA[mi] + C1[kk]);               \
        Af[buf][(mi) * 4 + 3] = lds_u32((sA) + rowA[mi] + 1024 + C1[kk]);        \
    } while (0)
    #define LDB2(buf, sB, kk, nj) do {                                           \
        Bf[buf][0] = lds_u32((sB) + rowB + (uint32_t)(nj) * 1024 + C0[kk]);      \
        Bf[buf][1] = lds_u32((sB) + rowB + (uint32_t)(nj) * 1024 + C1[kk]);      \
    } while (0)

    int s = 0, ph = 0;
    #pragma unroll 1
    for (int ks = 0; ks < 64; ks++) {
        WAIT_PAR(fullb + 8 * s, ph);
        uint32_t sA = base + (uint32_t)s * STAGE2_BYTES;
        OPAQUE(sA);
        uint32_t sB = sA + 16384;

        #pragma unroll
        for (int mi = 0; mi < 4; mi++) LDA4(0, sA, 0, mi);
        LDB2(0, sB, 0, 0);

        #pragma unroll
        for (int kk = 0; kk < 4; kk++) {
            #pragma unroll
            for (int nj = 0; nj < 8; nj++) {
                int grp = kk * 8 + nj;
                int cb = grp & 1;
                if (nj < 7)       LDB2(cb ^ 1, sB, kk, nj + 1);
                else if (kk < 3)  LDB2(cb ^ 1, sB, kk + 1, 0);
                if (kk < 3 && nj >= 4) LDA4((kk + 1) & 1, sA, kk + 1, nj - 4);
                int ab = kk & 1;
                #pragma unroll
                for (int mi = 0; mi < 4; mi++)
                    MMA_F16(acc[mi][nj], Af[ab][mi * 4 + 0], Af[ab][mi * 4 + 1],
                            Af[ab][mi * 4 + 2], Af[ab][mi * 4 + 3],
                            Bf[cb][0], Bf[cb][1]);
            }
        }
        if (lane == 0) MBAR_ARRIVE(emptb + 8 * s);
        if (tid == 0 && ks + (int)STAGES2 < 64) {
            WAIT_PAR(emptb + 8 * s, ph);
            uint32_t sb = base + (uint32_t)s * STAGE2_BYTES;
            MBAR_EXPECT_TX(fullb + 8 * s, STAGE2_BYTES);
            TMA2D(sb,         &tmA, (ks + (int)STAGES2) * 64, arow, fullb + 8 * s);
            TMA2D(sb + 16384, &tmB, (ks + (int)STAGES2) * 64, brow, fullb + 8 * s);
        }
        if (++s == (int)STAGES2) { s = 0; ph ^= 1; }
    }
    #undef LDA4
    #undef LDB2

    #pragma unroll
    for (int mi = 0; mi < 4; mi++) {
        int tok0 = mt * 128 + wm * 64 + mi * 16 + g;
        float* p0 = out + (size_t)(e * NT + tok0) * NH + nt * 128 + wn * 64;
        float* p1 = p0 + (size_t)8 * NH;
        #pragma unroll
        for (int nj = 0; nj < 8; nj++) {
            int colo = nj * 8 + 2 * tig;
            float2 v0 = {acc[mi][nj][0], acc[mi][nj][1]};
            float2 v1 = {acc[mi][nj][2], acc[mi][nj][3]};
            *reinterpret_cast<float2*>(p0 + colo) = v0;
            *reinterpret_cast<float2*>(p1 + colo) = v1;
        }
    }
}

// ============================================================================
// Host
// ============================================================================
typedef CUresult (*EncodeFn)(CUtensorMap*, CUtensorMapDataType, cuuint32_t, void*,
                             const cuuint64_t*, const cuuint64_t*, const cuuint32_t*,
                             const cuuint32_t*, CUtensorMapInterleave, CUtensorMapSwizzle,
                             CUtensorMapL2promotion, CUtensorMapFloatOOBfill);

static void encode2d(EncodeFn fn, CUtensorMap* m, void* p, CUtensorMapDataType dt,
                     uint64_t d0, uint64_t d1, uint64_t stride_bytes,
                     uint32_t b0, uint32_t b1) {
    cuuint64_t dims[2] = {d0, d1};
    cuuint64_t st[1]   = {stride_bytes};
    cuuint32_t box[2]  = {b0, b1};
    cuuint32_t es[2]   = {1, 1};
    fn(m, dt, 2, p, dims, st, box, es,
       CU_TENSOR_MAP_INTERLEAVE_NONE, CU_TENSOR_MAP_SWIZZLE_128B,
       CU_TENSOR_MAP_L2_PROMOTION_L2_128B, CU_TENSOR_MAP_FLOAT_OOB_FILL_NONE);
}

extern "C" void kernel_launch(void* const* d_in, const int* in_sizes, int n_in,
                              void* d_out, int out_size) {
    void* X  = d_in[0];  // (E*T, H) fp32
    void* W1 = d_in[1];  // (E, 2I, H) fp32
    void* W2 = d_in[2];  // (E, H, I) fp32

    void* pfn = nullptr;
    cudaDriverEntryPointQueryResult qr;
#if CUDART_VERSION >= 12050
    cudaGetDriverEntryPointByVersion("cuTensorMapEncodeTiled", &pfn, 12000,
                                     cudaEnableDefault, &qr);
#else
    cudaGetDriverEntryPoint("cuTensorMapEncodeTiled", &pfn, cudaEnableDefault, &qr);
#endif
    EncodeFn enc = (EncodeFn)pfn;

    void *xh, *w2h, *acth;
    cudaGetSymbolAddress(&xh,  g_xh);
    cudaGetSymbolAddress(&w2h, g_w2h);
    cudaGetSymbolAddress(&acth, g_act_h);

    CUtensorMap tA, tB32, tA2, tB2;
    encode2d(enc, &tA,   xh,  CU_TENSOR_MAP_DATA_TYPE_FLOAT16,
             NH, (uint64_t)NE * NT,     (uint64_t)NH * 2, 64, 128);
    encode2d(enc, &tB32, W1,  CU_TENSOR_MAP_DATA_TYPE_FLOAT32,
             NH, (uint64_t)NE * 2 * NI, (uint64_t)NH * 4, 32, 64);
    encode2d(enc, &tA2,  acth, CU_TENSOR_MAP_DATA_TYPE_FLOAT16,
             NI, (uint64_t)NE * NT,     (uint64_t)NI * 2, 64, 128);
    encode2d(enc, &tB2,  w2h, CU_TENSOR_MAP_DATA_TYPE_FLOAT16,
             NI, (uint64_t)NE * NH,     (uint64_t)NI * 2, 64, 128);

    cudaFuncSetAttribute(moe_gemm1, cudaFuncAttributeMaxDynamicSharedMemorySize, SMEM_ASK1);
    cudaFuncSetAttribute(moe_gemm2, cudaFuncAttributeMaxDynamicSharedMemorySize, SMEM_ASK2);

    // tiny prepass: X -> fp16 (~0.1GB traffic)
    int n4x = NE * NT * NH / 4;
    conv_x<<<4096, 256>>>((const float4*)X, (uint2*)xh, n4x);

    moe_gemm1<<<NE * 256, 128, SMEM_ASK1>>>(tA, tB32, (const float4*)W2);
    moe_gemm2<<<NE * 64, 128, SMEM_ASK2>>>(tA2, tB2, (float*)d_out);
}

// round 17
// speedup vs baseline: 1.6125x; 1.0563x over previous
#include <cuda_runtime.h>
#include <cuda.h>
#include <cuda_fp16.h>
#include <cstdint>

#define NE 16
#define NT 512
#define NH 2048
#define NI 4096

// scratch (allocation-free rule: __device__ globals)
__device__ __align__(1024) __half g_act_h[(size_t)NE * NT * NI];      // 67MB
__device__ __align__(1024) __half g_xh[(size_t)NE * NT * NH];         // 34MB

// ---------------- device helpers ----------------
__device__ __forceinline__ uint32_t smem_u32(const void* p) {
    uint32_t a;
    asm("{ .reg .u64 t; cvta.to.shared.u64 t, %1; cvt.u32.u64 %0, t; }" : "=r"(a) : "l"(p));
    return a;
}

#define MBAR_INIT(addr, cnt) \
    asm volatile("mbarrier.init.shared.b64 [%0], %1;" :: "r"(addr), "r"(cnt) : "memory")
#define MBAR_EXPECT_TX(addr, bytes) \
    asm volatile("mbarrier.arrive.expect_tx.shared.b64 _, [%0], %1;" :: "r"(addr), "r"(bytes) : "memory")
#define MBAR_ARRIVE(addr) \
    asm volatile("mbarrier.arrive.shared.b64 _, [%0];" :: "r"(addr) : "memory")
#define WAIT_PAR(addr, ph) do {                                                  \
    uint32_t _a = (addr), _p = (ph);                                             \
    asm volatile("{\n\t.reg .pred P;\n\t"                                        \
                 "WL_%=:\n\t"                                                    \
                 "mbarrier.try_wait.parity.shared.b64 P, [%0], %1, 0x989680;\n\t"\
                 "@!P bra WL_%=;\n\t}" :: "r"(_a), "r"(_p) : "memory");          \
} while (0)

#define OPAQUE(x) asm volatile("" : "+r"(x))

#define TMA2D(smem, map, x, y, mbar)                                                          \
    asm volatile("cp.async.bulk.tensor.2d.shared::cta.global.tile.mbarrier::complete_tx::bytes " \
                 "[%0], [%1, {%2, %3}], [%4];"                                                \
                 :: "r"(smem), "l"(map), "r"(x), "r"(y), "r"(mbar) : "memory")

__device__ __forceinline__ uint32_t lds_u32(uint32_t addr) {
    uint32_t v;
    asm("ld.shared.b32 %0, [%1];" : "=r"(v) : "r"(addr));
    return v;
}

// load 2 adjacent fp32 from smem, convert+pack to half2 (pure: schedulable)
__device__ __forceinline__ uint32_t lds2_h2(uint32_t addr) {
    uint32_t r;
    asm("{\n\t.reg .f32 x, y;\n\tld.shared.v2.f32 {x, y}, [%1];\n\t"
        ".reg .b16 a, b;\n\tcvt.rn.f16.f32 a, x;\n\tcvt.rn.f16.f32 b, y;\n\t"
        "mov.b32 %0, {a, b};\n\t}" : "=r"(r) : "r"(addr));
    return r;
}

__device__ __forceinline__ uint32_t pack_h2(float lo, float hi) {
    uint32_t r;
    asm("{\n\t.reg .b16 a, b;\n\tcvt.rn.f16.f32 a, %1;\n\tcvt.rn.f16.f32 b, %2;\n\t"
        "mov.b32 %0, {a, b};\n\t}" : "=r"(r) : "f"(lo), "f"(hi));
    return r;
}

#define MMA_F16(c, a0, a1, a2, a3, b0, b1)                                       \
    asm volatile("mma.sync.aligned.m16n8k16.row.col.f32.f16.f16.f32 "            \
                 "{%0,%1,%2,%3}, {%4,%5,%6,%7}, {%8,%9}, {%0,%1,%2,%3};"         \
                 : "+f"((c)[0]), "+f"((c)[1]), "+f"((c)[2]), "+f"((c)[3])        \
                 : "r"(a0), "r"(a1), "r"(a2), "r"(a3), "r"(b0), "r"(b1))

// Both GEMMs: A fp16 16KB + B fp32 32KB (2x 16KB k-halves) per stage; or for
// gemm1: A fp16 16KB + Bg fp32 16KB + Bu fp32 16KB.
static constexpr uint32_t STAGES = 2;
static constexpr uint32_t STAGE_BYTES = 49152;
static constexpr uint32_t SMEM_ASK = STAGES * STAGE_BYTES + 2048;

// ============================================================================
// X fp32 -> fp16 (tiny prepass, ~0.1GB traffic)
// ============================================================================
__global__ void conv_x(const float4* __restrict__ src, uint2* __restrict__ dst, int n4) {
    int i = blockIdx.x * blockDim.x + threadIdx.x;
    int stride = gridDim.x * blockDim.x;
    #pragma unroll 2
    for (; i < n4; i += stride) {
        float4 v = src[i];
        uint2 o;
        o.x = pack_h2(v.x, v.y);
        o.y = pack_h2(v.z, v.w);
        dst[i] = o;
    }
}

// ============================================================================
// GEMM1: act = up * silu(gate). CTA 128 tok x 64 act-cols, 4 warps,
// warp tile 64 x (32g + 32u), 2 CTAs/SM. A fp16 from g_xh; W1 read directly
// as fp32 via TMA, converted fp32->fp16 in the fragment path.
// ============================================================================
__global__ void __launch_bounds__(128, 2) moe_gemm1(
    const __grid_constant__ CUtensorMap tmA,
    const __grid_constant__ CUtensorMap tmB32) {
    extern __shared__ __align__(16) char dsm[];
    int tid = threadIdx.x;
    int b = blockIdx.x;
    int mt = b & 3, nt = (b >> 2) & 63, e = b >> 8;
    int arow = e * NT + mt * 128;
    int grow = e * (2 * NI) + nt * 64;
    int urow = grow + NI;

    uint32_t base = (smem_u32(dsm) + 1023u) & ~1023u;
    uint32_t fullb = base + STAGES * STAGE_BYTES;
    uint32_t emptb = fullb + 64;

    int wid = tid >> 5, lane = tid & 31;
    int g = lane >> 2, tig = lane & 3;
    int wm = wid >> 1, wn = wid & 1;
    uint32_t xr = (uint32_t)g << 4;

    if (tid == 0) {
        for (uint32_t s = 0; s < STAGES; s++) { MBAR_INIT(fullb + 8 * s, 1); MBAR_INIT(emptb + 8 * s, 4); }
        asm volatile("fence.proxy.async.shared::cta;" ::: "memory");
    }
    __syncthreads();

    if (tid == 0) {
        for (uint32_t c = 0; c < STAGES; c++) {
            uint32_t sb = base + c * STAGE_BYTES;
            MBAR_EXPECT_TX(fullb + 8 * c, STAGE_BYTES);
            TMA2D(sb,                 &tmA,   (int)c * 64,      arow, fullb + 8 * c);
            TMA2D(sb + 16384,         &tmB32, (int)c * 64,      grow, fullb + 8 * c);
            TMA2D(sb + 16384 + 8192,  &tmB32, (int)c * 64 + 32, grow, fullb + 8 * c);
            TMA2D(sb + 32768,         &tmB32, (int)c * 64,      urow, fullb + 8 * c);
            TMA2D(sb + 32768 + 8192,  &tmB32, (int)c * 64 + 32, urow, fullb + 8 * c);
        }
    }

    float accg[4][4][4], accu[4][4][4];
    #pragma unroll
    for (int i = 0; i < 4; i++)
        #pragma unroll
        for (int j = 0; j < 4; j++)
            #pragma unroll
            for (int q = 0; q < 4; q++) { accg[i][j][q] = 0.f; accu[i][j][q] = 0.f; }

    uint32_t rowA[4];
    #pragma unroll
    for (int mi = 0; mi < 4; mi++) rowA[mi] = (uint32_t)(wm * 64 + mi * 16 + g) * 128;
    uint32_t rowB = (uint32_t)(wn * 32 + g) * 128;

    uint32_t C0[4], C1[4];
    #pragma unroll
    for (int kk = 0; kk < 4; kk++) {
        C0[kk] = ((uint32_t)(kk * 32 + tig * 4)) ^ xr;
        C1[kk] = ((uint32_t)(kk * 32 + 16 + tig * 4)) ^ xr;
    }
    uint32_t D0[4], D1[4], TOFF[4];
    #pragma unroll
    for (int kk = 0; kk < 4; kk++) {
        D0[kk] = ((uint32_t)((kk & 1) * 64 + tig * 8)) ^ xr;
        D1[kk] = ((uint32_t)((kk & 1) * 64 + tig * 8 + 32)) ^ xr;
        TOFF[kk] = (uint32_t)(kk >> 1) * 8192;     // 8KB tiles (64 B-rows)
    }

    uint32_t Af[2][16], Bg[2][2], Bu[2][2];

    #define LDA4g(buf, sA, kk, mi) do {                                          \
        Af[buf][(mi) * 4 + 0] = lds_u32((sA) + rowA[mi] + C0[kk]);               \
        Af[buf][(mi) * 4 + 1] = lds_u32((sA) + rowA[mi] + 1024 + C0[kk]);        \
        Af[buf][(mi) * 4 + 2] = lds_u32((sA) + rowA[mi] + C1[kk]);               \
        Af[buf][(mi) * 4 + 3] = lds_u32((sA) + rowA[mi] + 1024 + C1[kk]);        \
    } while (0)
    #define LDGU(buf, sA, kk, nj) do {                                           \
        uint32_t _r = TOFF[kk] + rowB + (uint32_t)(nj) * 1024;                   \
        Bg[buf][0] = lds2_h2((sA) + 16384 + _r + D0[kk]);                        \
        Bg[buf][1] = lds2_h2((sA) + 16384 + _r + D1[kk]);                        \
        Bu[buf][0] = lds2_h2((sA) + 32768 + _r + D0[kk]);                        \
        Bu[buf][1] = lds2_h2((sA) + 32768 + _r + D1[kk]);                        \
    } while (0)

    int s = 0, ph = 0;
    #pragma unroll 1
    for (int ks = 0; ks < 32; ks++) {
        WAIT_PAR(fullb + 8 * s, ph);
        uint32_t sA = base + (uint32_t)s * STAGE_BYTES;
        OPAQUE(sA);

        #pragma unroll
        for (int mi = 0; mi < 4; mi++) LDA4g(0, sA, 0, mi);
        LDGU(0, sA, 0, 0);

        #pragma unroll
        for (int kk = 0; kk < 4; kk++) {
            #pragma unroll
            for (int nj = 0; nj < 4; nj++) {
                int grp = kk * 4 + nj;
                int cb = grp & 1;
                if (nj < 3)       LDGU(cb ^ 1, sA, kk, nj + 1);
                else if (kk < 3)  LDGU(cb ^ 1, sA, kk + 1, 0);
                if (kk < 3) LDA4g((kk + 1) & 1, sA, kk + 1, nj);
                int ab = kk & 1;
                #pragma unroll
                for (int mi = 0; mi < 4; mi++) {
                    MMA_F16(accg[mi][nj], Af[ab][mi * 4 + 0], Af[ab][mi * 4 + 1],
                            Af[ab][mi * 4 + 2], Af[ab][mi * 4 + 3],
                            Bg[cb][0], Bg[cb][1]);
                    MMA_F16(accu[mi][nj], Af[ab][mi * 4 + 0], Af[ab][mi * 4 + 1],
                            Af[ab][mi * 4 + 2], Af[ab][mi * 4 + 3],
                            Bu[cb][0], Bu[cb][1]);
                }
            }
        }
        if (lane == 0) MBAR_ARRIVE(emptb + 8 * s);
        if (tid == 0 && ks + (int)STAGES < 32) {
            WAIT_PAR(emptb + 8 * s, ph);
            uint32_t sb = base + (uint32_t)s * STAGE_BYTES;
            int kn = (ks + (int)STAGES) * 64;
            MBAR_EXPECT_TX(fullb + 8 * s, STAGE_BYTES);
            TMA2D(sb,                &tmA,   kn,      arow, fullb + 8 * s);
            TMA2D(sb + 16384,        &tmB32, kn,      grow, fullb + 8 * s);
            TMA2D(sb + 16384 + 8192, &tmB32, kn + 32, grow, fullb + 8 * s);
            TMA2D(sb + 32768,        &tmB32, kn,      urow, fullb + 8 * s);
            TMA2D(sb + 32768 + 8192, &tmB32, kn + 32, urow, fullb + 8 * s);
        }
        if (++s == (int)STAGES) { s = 0; ph ^= 1; }
    }
    #undef LDA4g
    #undef LDGU

    // Epilogue: SwiGLU -> fp16 act
    #pragma unroll
    for (int mi = 0; mi < 4; mi++) {
        int tok0 = mt * 128 + wm * 64 + mi * 16 + g;
        __half* p0 = g_act_h + (size_t)(e * NT + tok0) * NI + nt * 64 + wn * 32;
        __half* p1 = p0 + (size_t)8 * NI;
        #pragma unroll
        for (int nj = 0; nj < 4; nj++) {
            int colo = nj * 8 + 2 * tig;
            float v00, v01, v10, v11;
            float gg = accg[mi][nj][0], uu = accu[mi][nj][0];
            v00 = uu * gg / (1.0f + __expf(-gg));
            gg = accg[mi][nj][1]; uu = accu[mi][nj][1];
            v01 = uu * gg / (1.0f + __expf(-gg));
            gg = accg[mi][nj][2]; uu = accu[mi][nj][2];
            v10 = uu * gg / (1.0f + __expf(-gg));
            gg = accg[mi][nj][3]; uu = accu[mi][nj][3];
            v11 = uu * gg / (1.0f + __expf(-gg));
            *reinterpret_cast<uint32_t*>(p0 + colo) = pack_h2(v00, v01);
            *reinterpret_cast<uint32_t*>(p1 + colo) = pack_h2(v10, v11);
        }
    }
}

// ============================================================================
// GEMM2: out = act @ W2^T. CTA 128x128, 4 warps, warp tile 64x64, 2 CTAs/SM.
// A fp16 (act), W2 read DIRECTLY as fp32 via TMA (two 16KB k-half tiles per
// stage), converted in the fragment path. fp32 out.
// ============================================================================
__global__ void __launch_bounds__(128, 2) moe_gemm2(
    const __grid_constant__ CUtensorMap tmA,
    const __grid_constant__ CUtensorMap tmB32,
    float* __restrict__ out) {
    extern __shared__ __align__(16) char dsm[];
    uint32_t base = (smem_u32(dsm) + 1023u) & ~1023u;
    uint32_t fullb = base + STAGES * STAGE_BYTES;
    uint32_t emptb = fullb + 64;

    int tid = threadIdx.x, wid = tid >> 5, lane = tid & 31;
    int g = lane >> 2, tig = lane & 3;
    int wm = wid >> 1, wn = wid & 1;
    uint32_t xr = (uint32_t)g << 4;

    int b = blockIdx.x;
    int mt = b & 3, nt = (b >> 2) & 15, e = b >> 6;
    int arow = e * NT + mt * 128;
    int brow = e * NH + nt * 128;

    if (tid == 0) {
        for (uint32_t s = 0; s < STAGES; s++) { MBAR_INIT(fullb + 8 * s, 1); MBAR_INIT(emptb + 8 * s, 4); }
        asm volatile("fence.proxy.async.shared::cta;" ::: "memory");
    }
    __syncthreads();

    // stage: A fp16 @0 (16KB, k=64), B fp32 @16384 (2x 16KB tiles, k=32+32)
    if (tid == 0) {
        for (uint32_t c = 0; c < STAGES; c++) {
            uint32_t sb = base + c * STAGE_BYTES;
            MBAR_EXPECT_TX(fullb + 8 * c, STAGE_BYTES);
            TMA2D(sb,                 &tmA,   (int)c * 64,      arow, fullb + 8 * c);
            TMA2D(sb + 16384,         &tmB32, (int)c * 64,      brow, fullb + 8 * c);
            TMA2D(sb + 16384 + 16384, &tmB32, (int)c * 64 + 32, brow, fullb + 8 * c);
        }
    }

    float acc[4][8][4];
    #pragma unroll
    for (int i = 0; i < 4; i++)
        #pragma unroll
        for (int j = 0; j < 8; j++)
            #pragma unroll
            for (int q = 0; q < 4; q++) acc[i][j][q] = 0.f;

    uint32_t rowA[4];
    #pragma unroll
    for (int mi = 0; mi < 4; mi++) rowA[mi] = (uint32_t)(wm * 64 + mi * 16 + g) * 128;
    uint32_t rowB = (uint32_t)(wn * 64 + g) * 128;

    uint32_t C0[4], C1[4];
    #pragma unroll
    for (int kk = 0; kk < 4; kk++) {
        C0[kk] = ((uint32_t)(kk * 32 + tig * 4)) ^ xr;
        C1[kk] = ((uint32_t)(kk * 32 + 16 + tig * 4)) ^ xr;
    }
    uint32_t D0[4], D1[4], TOFF[4];
    #pragma unroll
    for (int kk = 0; kk < 4; kk++) {
        D0[kk] = ((uint32_t)((kk & 1) * 64 + tig * 8)) ^ xr;
        D1[kk] = ((uint32_t)((kk & 1) * 64 + tig * 8 + 32)) ^ xr;
        TOFF[kk] = (uint32_t)(kk >> 1) * 16384;    // 16KB tiles (128 B-rows)
    }

    uint32_t Af[2][16], Bf[2][2];

    #define LDA4(buf, sA, kk, mi) do {                                           \
        Af[buf][(mi) * 4 + 0] = lds_u32((sA) + rowA[mi] + C0[kk]);               \
        Af[buf][(mi) * 4 + 1] = lds_u32((sA) + rowA[mi] + 1024 + C0[kk]);        \
        Af[buf][(mi) * 4 + 2] = lds_u32((sA) + rowA[mi] + C1[kk]);               \
        Af[buf][(mi) * 4 + 3] = lds_u32((sA) + rowA[mi] + 1024 + C1[kk]);        \
    } while (0)
    #define LDB2(buf, sA, kk, nj) do {                                           \
        uint32_t _r = TOFF[kk] + rowB + (uint32_t)(nj) * 1024;                   \
        Bf[buf][0] = lds2_h2((sA) + 16384 + _r + D0[kk]);                        \
        Bf[buf][1] = lds2_h2((sA) + 16384 + _r + D1[kk]);                        \
    } while (0)

    int s = 0, ph = 0;
    #pragma unroll 1
    for (int ks = 0; ks < 64; ks++) {
        WAIT_PAR(fullb + 8 * s, ph);
        uint32_t sA = base + (uint32_t)s * STAGE_BYTES;
        OPAQUE(sA);

        #pragma unroll
        for (int mi = 0; mi < 4; mi++) LDA4(0, sA, 0, mi);
        LDB2(0, sA, 0, 0);

        #pragma unroll
        for (int kk = 0; kk < 4; kk++) {
            #pragma unroll
            for (int nj = 0; nj < 8; nj++) {
                int grp = kk * 8 + nj;
                int cb = grp & 1;
                if (nj < 7)       LDB2(cb ^ 1, sA, kk, nj + 1);
                else if (kk < 3)  LDB2(cb ^ 1, sA, kk + 1, 0);
                if (kk < 3 && nj >= 4) LDA4((kk + 1) & 1, sA, kk + 1, nj - 4);
                int ab = kk & 1;
                #pragma unroll
                for (int mi = 0; mi < 4; mi++)
                    MMA_F16(acc[mi][nj], Af[ab][mi * 4 + 0], Af[ab][mi * 4 + 1],
                            Af[ab][mi * 4 + 2], Af[ab][mi * 4 + 3],
                            Bf[cb][0], Bf[cb][1]);
            }
        }
        if (lane == 0) MBAR_ARRIVE(emptb + 8 * s);
        if (tid == 0 && ks + (int)STAGES < 64) {
            WAIT_PAR(emptb + 8 * s, ph);
            uint32_t sb = base + (uint32_t)s * STAGE_BYTES;
            int kn = (ks + (int)STAGES) * 64;
            MBAR_EXPECT_TX(fullb + 8 * s, STAGE_BYTES);
            TMA2D(sb,                 &tmA,   kn,      arow, fullb + 8 * s);
            TMA2D(sb + 16384,         &tmB32, kn,      brow, fullb + 8 * s);
            TMA2D(sb + 16384 + 16384, &tmB32, kn + 32, brow, fullb + 8 * s);
        }
        if (++s == (int)STAGES) { s = 0; ph ^= 1; }
    }
    #undef LDA4
    #undef LDB2

    #pragma unroll
    for (int mi = 0; mi < 4; mi++) {
        int tok0 = mt * 128 + wm * 64 + mi * 16 + g;
        float* p0 = out + (size_t)(e * NT + tok0) * NH + nt * 128 + wn * 64;
        float* p1 = p0 + (size_t)8 * NH;
        #pragma unroll
        for (int nj = 0; nj < 8; nj++) {
            int colo = nj * 8 + 2 * tig;
            float2 v0 = {acc[mi][nj][0], acc[mi][nj][1]};
            float2 v1 = {acc[mi][nj][2], acc[mi][nj][3]};
            *reinterpret_cast<float2*>(p0 + colo) = v0;
            *reinterpret_cast<float2*>(p1 + colo) = v1;
        }
    }
}

// ============================================================================
// Host
// ============================================================================
typedef CUresult (*EncodeFn)(CUtensorMap*, CUtensorMapDataType, cuuint32_t, void*,
                             const cuuint64_t*, const cuuint64_t*, const cuuint32_t*,
                             const cuuint32_t*, CUtensorMapInterleave, CUtensorMapSwizzle,
                             CUtensorMapL2promotion, CUtensorMapFloatOOBfill);

static void encode2d(EncodeFn fn, CUtensorMap* m, void* p, CUtensorMapDataType dt,
                     uint64_t d0, uint64_t d1, uint64_t stride_bytes,
                     uint32_t b0, uint32_t b1) {
    cuuint64_t dims[2] = {d0, d1};
    cuuint64_t st[1]   = {stride_bytes};
    cuuint32_t box[2]  = {b0, b1};
    cuuint32_t es[2]   = {1, 1};
    fn(m, dt, 2, p, dims, st, box, es,
       CU_TENSOR_MAP_INTERLEAVE_NONE, CU_TENSOR_MAP_SWIZZLE_128B,
       CU_TENSOR_MAP_L2_PROMOTION_L2_128B, CU_TENSOR_MAP_FLOAT_OOB_FILL_NONE);
}

extern "C" void kernel_launch(void* const* d_in, const int* in_sizes, int n_in,
                              void* d_out, int out_size) {
    void* X  = d_in[0];  // (E*T, H) fp32
    void* W1 = d_in[1];  // (E, 2I, H) fp32
    void* W2 = d_in[2];  // (E, H, I) fp32

    void* pfn = nullptr;
    cudaDriverEntryPointQueryResult qr;
#if CUDART_VERSION >= 12050
    cudaGetDriverEntryPointByVersion("cuTensorMapEncodeTiled", &pfn, 12000,
                                     cudaEnableDefault, &qr);
#else
    cudaGetDriverEntryPoint("cuTensorMapEncodeTiled", &pfn, cudaEnableDefault, &qr);
#endif
    EncodeFn enc = (EncodeFn)pfn;

    void *xh, *acth;
    cudaGetSymbolAddress(&xh,  g_xh);
    cudaGetSymbolAddress(&acth, g_act_h);

    CUtensorMap tA, tB32, tA2, tB2_32;
    encode2d(enc, &tA,    xh,  CU_TENSOR_MAP_DATA_TYPE_FLOAT16,
             NH, (uint64_t)NE * NT,     (uint64_t)NH * 2, 64, 128);
    encode2d(enc, &tB32,  W1,  CU_TENSOR_MAP_DATA_TYPE_FLOAT32,
             NH, (uint64_t)NE * 2 * NI, (uint64_t)NH * 4, 32, 64);
    encode2d(enc, &tA2,   acth, CU_TENSOR_MAP_DATA_TYPE_FLOAT16,
             NI, (uint64_t)NE * NT,     (uint64_t)NI * 2, 64, 128);
    encode2d(enc, &tB2_32, W2, CU_TENSOR_MAP_DATA_TYPE_FLOAT32,
             NI, (uint64_t)NE * NH,     (uint64_t)NI * 4, 32, 128);

    cudaFuncSetAttribute(moe_gemm1, cudaFuncAttributeMaxDynamicSharedMemorySize, SMEM_ASK);
    cudaFuncSetAttribute(moe_gemm2, cudaFuncAttributeMaxDynamicSharedMemorySize, SMEM_ASK);

    // tiny prepass: X -> fp16 (~0.1GB traffic)
    int n4x = NE * NT * NH / 4;
    conv_x<<<4096, 256>>>((const float4*)X, (uint2*)xh, n4x);

    moe_gemm1<<<NE * 256, 128, SMEM_ASK>>>(tA, tB32);
    moe_gemm2<<<NE * 64, 128, SMEM_ASK>>>(tA2, tB2_32, (float*)d_out);
}